// round 5
// baseline (speedup 1.0000x reference)
#include <cuda_runtime.h>
#include <cuda_bf16.h>
#include <math.h>

// Problem sizes
#define NB    64
#define NS    256
#define NC    16
#define ND    512
#define N4D   2048
#define NVIS  16384            // NB*NS
#define VOCABI 20000

// Recurrence config
#define NCTA_REC 128
#define UNITS    4             // hidden units per CTA
#define GROWS    16            // gate rows per CTA (UNITS*4)
#define WSTRIDE  260           // u32 stride for a 512-bf16 W row (+8 bf16 pad) = 1040 B
#define GSTRIDE  20            // float stride for gates smem rows (16 + pad)
#define HBUF     65536         // bytes per h buffer per array (64 rows x 1024 B)

// smem byte offsets (lstm_rec)
#define SM_W    0
#define SM_WSZ  (2 * GROWS * WSTRIDE * 4)          // 33280, 128-aligned
#define SM_HH   SM_WSZ                              // 33280
#define SM_HL   (SM_HH + HBUF)                      // 98816
#define SM_G    (SM_HL + HBUF)                      // 164352
#define SM_MBAR (SM_G + NB * GSTRIDE * 4)           // 169472
#define SM_TOT  (SM_MBAR + 128)                     // 169600

// GEMM config
#define GAST_B   80            // bytes per smem row (32 bf16 + 8 pad)
#define GARR_B   10240         // bytes per array per stage (128 rows * 80)
#define GSTAGE_B 40960         // 4 arrays
#define GNSTAGE  3

// ---------------- device scratch (static globals: no allocation) ----------------
__device__ __nv_bfloat16 g_Xhi[NVIS * ND];
__device__ __nv_bfloat16 g_Xlo[NVIS * ND];
__device__ __nv_bfloat16 g_Wih_hi[N4D * ND];
__device__ __nv_bfloat16 g_Wih_lo[N4D * ND];
__device__ __nv_bfloat16 g_Whh_hi[N4D * ND];
__device__ __nv_bfloat16 g_Whh_lo[N4D * ND];
__device__ float         g_Xg[(size_t)NVIS * N4D];        // 134 MB
__device__ __align__(128) unsigned char g_h_hi[2 * HBUF]; // double buffered, swizzled image
__device__ __align__(128) unsigned char g_h_lo[2 * HBUF];
__device__ float         g_final[NB * ND];
__device__ unsigned      g_arrive;

// ---------------- helpers ----------------
__device__ __forceinline__ void mma_bf16(float* c, const unsigned* a, const unsigned* b) {
    asm volatile(
        "mma.sync.aligned.m16n8k16.row.col.f32.bf16.bf16.f32 "
        "{%0,%1,%2,%3}, {%4,%5,%6,%7}, {%8,%9}, {%0,%1,%2,%3};\n"
        : "+f"(c[0]), "+f"(c[1]), "+f"(c[2]), "+f"(c[3])
        : "r"(a[0]), "r"(a[1]), "r"(a[2]), "r"(a[3]), "r"(b[0]), "r"(b[1]));
}

__device__ __forceinline__ void ldsm4(unsigned* r, unsigned saddr) {
    asm volatile("ldmatrix.sync.aligned.m8n8.x4.shared.b16 {%0,%1,%2,%3}, [%4];"
                 : "=r"(r[0]), "=r"(r[1]), "=r"(r[2]), "=r"(r[3]) : "r"(saddr));
}
__device__ __forceinline__ void ldsm2(unsigned* r, unsigned saddr) {
    asm volatile("ldmatrix.sync.aligned.m8n8.x2.shared.b16 {%0,%1}, [%2];"
                 : "=r"(r[0]), "=r"(r[1]) : "r"(saddr));
}
__device__ __forceinline__ void cp16(unsigned s, const void* g) {
    asm volatile("cp.async.cg.shared.global [%0], [%1], 16;\n" :: "r"(s), "l"(g));
}
__device__ __forceinline__ void cp_commit() {
    asm volatile("cp.async.commit_group;\n" ::: "memory");
}
template<int N> __device__ __forceinline__ void cp_wait() {
    asm volatile("cp.async.wait_group %0;\n" :: "n"(N) : "memory");
}

// bulk copy: gmem -> smem, completes on mbarrier (UBLKCP)
__device__ __forceinline__ void bulk_g2s(unsigned dst, const void* src, unsigned bytes,
                                         unsigned mbar) {
    asm volatile(
        "cp.async.bulk.shared::cta.global.mbarrier::complete_tx::bytes [%0], [%1], %2, [%3];"
        :: "r"(dst), "l"(src), "r"(bytes), "r"(mbar) : "memory");
}
__device__ __forceinline__ void mbar_init(unsigned mbar, unsigned cnt) {
    asm volatile("mbarrier.init.shared.b64 [%0], %1;" :: "r"(mbar), "r"(cnt) : "memory");
}
__device__ __forceinline__ void mbar_expect_tx(unsigned mbar, unsigned tx) {
    asm volatile("mbarrier.arrive.expect_tx.shared.b64 _, [%0], %1;" :: "r"(mbar), "r"(tx) : "memory");
}
__device__ __forceinline__ void mbar_wait(unsigned mbar, unsigned parity) {
    asm volatile(
        "{\n\t.reg .pred P;\n"
        "WLP%=:\n\t"
        "mbarrier.try_wait.parity.shared::cta.b64 P, [%0], %1, 0x989680;\n\t"
        "@P bra.uni WDN%=;\n\t"
        "bra.uni WLP%=;\n"
        "WDN%=:\n\t}"
        :: "r"(mbar), "r"(parity) : "memory");
}

__device__ __forceinline__ void arrive_release(unsigned* p) {
    asm volatile("red.release.gpu.global.add.u32 [%0], 1;" :: "l"(p) : "memory");
}
__device__ __forceinline__ unsigned ld_acquire(const unsigned* p) {
    unsigned v;
    asm volatile("ld.acquire.gpu.global.u32 %0, [%1];" : "=r"(v) : "l"(p) : "memory");
    return v;
}

__device__ __forceinline__ void split_bf16(float v, __nv_bfloat16& hi, __nv_bfloat16& lo) {
    hi = __float2bfloat16_rn(v);
    lo = __float2bfloat16_rn(v - __bfloat162float(hi));
}

__device__ __forceinline__ float sigf(float x) { return 1.f / (1.f + expf(-x)); }

// ---------------- kernel 1: weights -> hi/lo bf16 ----------------
__global__ void prep_weights(const float* __restrict__ wih, const float* __restrict__ whh) {
    int i = blockIdx.x * 256 + threadIdx.x;
    if (i < N4D * ND) {
        split_bf16(wih[i], g_Wih_hi[i], g_Wih_lo[i]);
        split_bf16(whh[i], g_Whh_hi[i], g_Whh_lo[i]);
    }
}

// ---------------- kernel 2: embedding-bag sum -> X (hi/lo bf16) ----------------
__global__ void embed_kernel(const int* __restrict__ seqs, const float* __restrict__ emb) {
    int vis = blockIdx.x;          // 0..16383
    int t   = threadIdx.x;         // 0..127
    const int* s = seqs + vis * NC;
    float a0 = 0.f, a1 = 0.f, a2 = 0.f, a3 = 0.f;
#pragma unroll
    for (int c = 0; c < NC; c++) {
        int idx = s[c];
        if (idx >= VOCABI) continue;          // padding row -> zero
        const float* row = emb + (size_t)idx * ND;
        a0 += row[t];
        a1 += row[t + 128];
        a2 += row[t + 256];
        a3 += row[t + 384];
    }
    int base = vis * ND + t;
    split_bf16(a0, g_Xhi[base],       g_Xlo[base]);
    split_bf16(a1, g_Xhi[base + 128], g_Xlo[base + 128]);
    split_bf16(a2, g_Xhi[base + 256], g_Xlo[base + 256]);
    split_bf16(a3, g_Xhi[base + 384], g_Xlo[base + 384]);
}

// ---------------- kernel 3: input GEMM  Xg = X @ W_ih^T ----------------
// CTA tile 128x128, 512 threads = 16 warps (4m x 4n), warp tile 32x32.
// 3-stage cp.async pipeline, K=32 per stage, ldmatrix operand loads.
__global__ void __launch_bounds__(512, 1) input_gemm() {
    extern __shared__ unsigned gsm[];
    unsigned sbase = (unsigned)__cvta_generic_to_shared(gsm);

    int t = threadIdx.x;
    int w = t >> 5, lane = t & 31;
    int wm = w >> 2, wn = w & 3;
    int g = lane >> 2, q = lane & 3;
    int m0 = blockIdx.y * 128, n0 = blockIdx.x * 128;

    int lrow = t >> 2;             // 0..127
    int lch  = t & 3;              // 16B chunk

    const __nv_bfloat16* pAh = g_Xhi    + (size_t)(m0 + lrow) * ND + lch * 8;
    const __nv_bfloat16* pAl = g_Xlo    + (size_t)(m0 + lrow) * ND + lch * 8;
    const __nv_bfloat16* pBh = g_Wih_hi + (size_t)(n0 + lrow) * ND + lch * 8;
    const __nv_bfloat16* pBl = g_Wih_lo + (size_t)(n0 + lrow) * ND + lch * 8;
    unsigned sdst = sbase + lrow * GAST_B + lch * 16;

    float acc[2][4][4];
#pragma unroll
    for (int i = 0; i < 2; i++)
#pragma unroll
        for (int j = 0; j < 4; j++)
#pragma unroll
            for (int k = 0; k < 4; k++) acc[i][j][k] = 0.f;

    // prologue: stage 0 and 1
#pragma unroll
    for (int ps = 0; ps < 2; ps++) {
        unsigned d = sdst + ps * GSTAGE_B;
        const int ko = ps * 32;
        cp16(d,              pAh + ko);
        cp16(d + GARR_B,     pAl + ko);
        cp16(d + 2 * GARR_B, pBh + ko);
        cp16(d + 3 * GARR_B, pBl + ko);
        cp_commit();
    }

    // ldmatrix lane address components
    int arow = wm * 32 + (lane & 15);
    int acol = (lane >> 4) * 16;            // byte offset within k-chunk
    int brow = wn * 32 + (lane & 7) + (lane >> 4) * 8;
    int bcol = ((lane >> 3) & 1) * 16;

    int buf = 0;                   // = s % 3
    int nbuf = 2;                  // = (s+2) % 3
    for (int s = 0; s < 16; s++) {
        cp_wait<1>();              // group s complete (s+1 may pend)
        __syncthreads();           // all threads done reading buf (s-1)%3
        if (s + 2 < 16) {
            unsigned d = sdst + nbuf * GSTAGE_B;
            const int ko = (s + 2) * 32;
            cp16(d,              pAh + ko);
            cp16(d + GARR_B,     pAl + ko);
            cp16(d + 2 * GARR_B, pBh + ko);
            cp16(d + 3 * GARR_B, pBl + ko);
            cp_commit();
        }
        unsigned base = sbase + buf * GSTAGE_B;
#pragma unroll
        for (int kk = 0; kk < 2; kk++) {
            unsigned koff = kk * 32;
            unsigned ah[2][4], al[2][4], bh[2][4], bl[2][4];
#pragma unroll
            for (int i = 0; i < 2; i++) {
                unsigned ad = base + (arow + i * 16) * GAST_B + koff + acol;
                ldsm4(ah[i], ad);
                ldsm4(al[i], ad + GARR_B);
            }
#pragma unroll
            for (int j2 = 0; j2 < 2; j2++) {
                unsigned bd = base + 2 * GARR_B + (brow + j2 * 16) * GAST_B + koff + bcol;
                ldsm4(bh[j2], bd);
                ldsm4(bl[j2], bd + GARR_B);
            }
#pragma unroll
            for (int i = 0; i < 2; i++)
#pragma unroll
                for (int j = 0; j < 4; j++) {
                    unsigned bhf[2] = { bh[j >> 1][(j & 1) * 2], bh[j >> 1][(j & 1) * 2 + 1] };
                    unsigned blf[2] = { bl[j >> 1][(j & 1) * 2], bl[j >> 1][(j & 1) * 2 + 1] };
                    mma_bf16(acc[i][j], ah[i], bhf);
                    mma_bf16(acc[i][j], ah[i], blf);
                    mma_bf16(acc[i][j], al[i], bhf);
                }
        }
        buf = (buf == 2) ? 0 : buf + 1;
        nbuf = (nbuf == 2) ? 0 : nbuf + 1;
    }

#pragma unroll
    for (int i = 0; i < 2; i++) {
        int r0 = m0 + wm * 32 + i * 16 + g;
#pragma unroll
        for (int j = 0; j < 4; j++) {
            int cc = n0 + wn * 32 + j * 8 + 2 * q;
            *(float2*)(g_Xg + (size_t)r0 * N4D + cc)       = make_float2(acc[i][j][0], acc[i][j][1]);
            *(float2*)(g_Xg + (size_t)(r0 + 8) * N4D + cc) = make_float2(acc[i][j][2], acc[i][j][3]);
        }
    }
}

// ---------------- kernel 4: reset state + barrier ----------------
__global__ void reset_kernel() {
    int i = blockIdx.x * 256 + threadIdx.x;
    if (i < 2 * HBUF / 4) {
        ((unsigned*)g_h_hi)[i] = 0u;
        ((unsigned*)g_h_lo)[i] = 0u;
    }
    if (i == 0) g_arrive = 0u;
}

// ---------------- kernel 5: persistent LSTM recurrence ----------------
// 128 CTAs (1/SM), 256 threads. Each CTA owns 4 units (16 gate rows).
// W_hh slice in SMEM for all 256 steps. h double-buffered in GMEM, stored in
// the exact swizzled smem image (K-major 128B chunks, XOR-swizzled by row&7),
// staged per step with TWO cp.async.bulk copies (no per-16B issue cost).
__global__ void __launch_bounds__(256, 1) lstm_rec(const int* __restrict__ lengths) {
    extern __shared__ unsigned smem[];
    char* smc = (char*)smem;
    unsigned* sWh = (unsigned*)(smc + SM_W);            // GROWS*WSTRIDE u32 (hi), then lo
    unsigned* sWl = sWh + GROWS * WSTRIDE;
    float*  sG = (float*)(smc + SM_G);                  // NB * GSTRIDE

    unsigned sb = (unsigned)__cvta_generic_to_shared(smc);
    unsigned sWh_b = sb + SM_W;
    unsigned sHh_b = sb + SM_HH;
    unsigned mbar  = sb + SM_MBAR;

    int t = threadIdx.x, cta = blockIdx.x;
    int w = t >> 5, lane = t & 31;
    int wm = w >> 1, wn = w & 1;
    int g = lane >> 2, q = lane & 3;

    // load W_hh slice into smem (hi/lo). slot s: u=s>>2, gate=s&3.
    const unsigned* Whi = (const unsigned*)g_Whh_hi;
    const unsigned* Wlo = (const unsigned*)g_Whh_lo;
    for (int i = t; i < GROWS * 256; i += 256) {
        int s = i >> 8, kw = i & 255;
        int u = s >> 2, gate = s & 3;
        int grow = gate * ND + cta * UNITS + u;
        sWh[s * WSTRIDE + kw] = Whi[grow * 256 + kw];
        sWl[s * WSTRIDE + kw] = Wlo[grow * 256 + kw];
    }
    if (t == 0) mbar_init(mbar, 1);

    // epilogue ownership: one (batch, unit) pair per thread
    int bb = t >> 2, uu = t & 3;
    int len0 = lengths[bb] - 1;
    float cst = 0.f;
    int jglob = cta * UNITS + uu;

    // swizzled h write offset for (bb, jglob), byte units
    unsigned hoff;
    {
        int c = jglob >> 6;                 // 128B chunk
        int u = (jglob >> 3) & 7;           // 16B unit within chunk
        int lo4 = (jglob * 2) & 15;
        hoff = ((unsigned)(c * 64 + bb) << 7) + ((unsigned)(u ^ (bb & 7)) << 4) + lo4;
    }

    // ldmatrix A lane constants: row r, k-half
    int ar = wm * 16 + (lane & 15);
    int ahalf = lane >> 4;
    unsigned arbase = sHh_b + (unsigned)ar * 128;
    unsigned arx = (unsigned)(ar & 7);

    // ldmatrix B lane addresses (W padded layout, unchanged)
    unsigned boff = sWh_b + (unsigned)(wn * 8 + (lane & 7)) * (WSTRIDE * 4) + ((lane >> 3) & 1) * 16;
    const unsigned HLO = HBUF;                   // byte offset sHh -> sHl
    const unsigned WLO = GROWS * WSTRIDE * 4;    // byte offset sWh -> sWl

    // prefetch Xg for step 0
    size_t xb0 = ((size_t)bb * NS + 0) * N4D + jglob;
    float x0 = __ldcg(g_Xg + xb0);
    float x1 = __ldcg(g_Xg + xb0 + 512);
    float x2 = __ldcg(g_Xg + xb0 + 1024);
    float x3 = __ldcg(g_Xg + xb0 + 1536);

    __syncthreads();

    for (int step = 0; step < NS; step++) {
        int rd = step & 1;
        int wr = rd ^ 1;

        // ---- stage h: two bulk copies (hi, lo), mbarrier completion ----
        if (t == 0) {
            mbar_expect_tx(mbar, 2 * HBUF);
            bulk_g2s(sHh_b,       g_h_hi + rd * HBUF, HBUF, mbar);
            bulk_g2s(sHh_b + HLO, g_h_lo + rd * HBUF, HBUF, mbar);
        }
        mbar_wait(mbar, (unsigned)(step & 1));

        // ---- mma: gates = h @ Wslice^T (hi/lo split, fp32 acc) ----
        float acc[4] = {0.f, 0.f, 0.f, 0.f};
#pragma unroll
        for (int kc = 0; kc < 32; kc++) {
            // A address: logical (row ar, 16B-unit kidx = 2*kc + ahalf)
            int kidx = 2 * kc + ahalf;
            unsigned aaddr = arbase + (unsigned)((kidx >> 3) << 13)
                                    + ((((unsigned)(kidx & 7)) ^ arx) << 4);
            unsigned ah[4], al[4], bh[2], bl[2];
            ldsm4(ah, aaddr);
            ldsm4(al, aaddr + HLO);
            ldsm2(bh, boff + kc * 32);
            ldsm2(bl, boff + kc * 32 + WLO);
            mma_bf16(acc, ah, bh);
            mma_bf16(acc, ah, bl);
            mma_bf16(acc, al, bh);
        }

        {
            int r0 = wm * 16 + g, c0 = wn * 8 + 2 * q;
            *(float2*)(sG + r0 * GSTRIDE + c0)       = make_float2(acc[0], acc[1]);
            *(float2*)(sG + (r0 + 8) * GSTRIDE + c0) = make_float2(acc[2], acc[3]);
        }
        __syncthreads();

        // ---- epilogue ----
        {
            const float* gp = sG + bb * GSTRIDE + uu * 4;
            float gi = gp[0] + x0;
            float gf = gp[1] + x1;
            float gg = gp[2] + x2;
            float go = gp[3] + x3;
            float iv = sigf(gi);
            float fv = sigf(gf);
            float gv = tanhf(gg);
            float ov = sigf(go);
            float c = fv * cst + iv * gv;
            cst = c;
            float hv = ov * tanhf(c);
            __nv_bfloat16 hb, lb;
            split_bf16(hv, hb, lb);
            *(__nv_bfloat16*)(g_h_hi + wr * HBUF + hoff) = hb;
            *(__nv_bfloat16*)(g_h_lo + wr * HBUF + hoff) = lb;
            if (step == len0) g_final[bb * ND + jglob] = hv;
        }
        __syncthreads();            // all h writes issued (+ sG reads done)

        // ---- arrive (release; bar.sync ordered all CTA writes before it) ----
        if (t == 0) arrive_release(&g_arrive);

        // ---- prefetch next step's Xg while barrier settles ----
        {
            int nstep = (step + 1 < NS) ? step + 1 : 0;
            size_t xb = ((size_t)bb * NS + nstep) * N4D + jglob;
            x0 = __ldcg(g_Xg + xb);
            x1 = __ldcg(g_Xg + xb + 512);
            x2 = __ldcg(g_Xg + xb + 1024);
            x3 = __ldcg(g_Xg + xb + 1536);
        }

        // ---- wait ----
        if (t == 0) {
            unsigned target = (unsigned)NCTA_REC * (unsigned)(step + 1);
            while (ld_acquire(&g_arrive) < target) { }
        }
        __syncthreads();
    }
}

// ---------------- kernel 6: output projection ----------------
__global__ void final_out(const float* __restrict__ w_out, const float* __restrict__ b_out,
                          float* __restrict__ out) {
    int b = blockIdx.x;
    int t = threadIdx.x;
    int r = t >> 5, lane = t & 31;
    float s = 0.f;
    for (int k = lane; k < ND; k += 32)
        s += g_final[b * ND + k] * w_out[r * ND + k];
#pragma unroll
    for (int off = 16; off; off >>= 1) s += __shfl_down_sync(0xffffffffu, s, off);
    if (lane == 0) out[b * 2 + r] = s + b_out[r];
}

// ---------------- launch ----------------
extern "C" void kernel_launch(void* const* d_in, const int* in_sizes, int n_in,
                              void* d_out, int out_size) {
    const int*   seqs    = (const int*)d_in[0];
    const int*   lengths = (const int*)d_in[1];
    const float* emb     = (const float*)d_in[2];
    const float* wih     = (const float*)d_in[3];
    const float* whh     = (const float*)d_in[4];
    const float* wout    = (const float*)d_in[5];
    const float* bout    = (const float*)d_in[6];
    float* out = (float*)d_out;

    cudaFuncSetAttribute(lstm_rec, cudaFuncAttributeMaxDynamicSharedMemorySize, SM_TOT);
    const int gemm_smem = GNSTAGE * GSTAGE_B;
    cudaFuncSetAttribute(input_gemm, cudaFuncAttributeMaxDynamicSharedMemorySize, gemm_smem);

    prep_weights<<<4096, 256>>>(wih, whh);
    embed_kernel<<<NVIS, 128>>>(seqs, emb);
    dim3 gg(N4D / 128, NVIS / 128);
    input_gemm<<<gg, 512, gemm_smem>>>();
    reset_kernel<<<128, 256>>>();
    lstm_rec<<<NCTA_REC, 256, SM_TOT>>>(lengths);
    final_out<<<NB, 64>>>(wout, bout, out);
}

// round 7
// speedup vs baseline: 1.6767x; 1.6767x over previous
#include <cuda_runtime.h>
#include <cuda_bf16.h>
#include <cuda_fp16.h>
#include <math.h>

// Problem sizes
#define NB    64
#define NS    256
#define NC    16
#define ND    512
#define N4D   2048
#define NVIS  16384            // NB*NS
#define VOCABI 20000

// Recurrence config
#define NCTA_REC 128
#define UNITS    4             // hidden units per CTA
#define GROWS    16            // gate rows per CTA (UNITS*4)
#define WSTRIDE  260           // u32 stride for a 512-half row (+16B pad) = 1040 B
#define GSTRIDE  20            // float stride for gates smem rows (16 + pad)

// lstm_rec smem byte offsets
#define SM_W    0
#define SM_WSZ  (2 * GROWS * WSTRIDE * 4)          // 33280 (hi + lo W arrays)
#define SM_H    SM_WSZ                              // 33280
#define SM_HSZ  (NB * WSTRIDE * 4)                  // 66560
#define SM_G    (SM_H + SM_HSZ)                     // 99840
#define SM_TOT  (SM_G + NB * GSTRIDE * 4)           // 104960

// GEMM config
#define GAST_B   80            // bytes per smem row (32 bf16 + 8 pad)
#define GARR_B   10240         // bytes per array per stage (128 rows * 80)
#define GSTAGE_B 40960         // 4 arrays
#define GNSTAGE  3

// ---------------- device scratch (static globals: no allocation) ----------------
__device__ __nv_bfloat16 g_Xhi[NVIS * ND];
__device__ __nv_bfloat16 g_Xlo[NVIS * ND];
__device__ __nv_bfloat16 g_Wih_hi[N4D * ND];
__device__ __nv_bfloat16 g_Wih_lo[N4D * ND];
__device__ __half        g_Wh16hi[N4D * ND];
__device__ __half        g_Wh16lo[N4D * ND];
__device__ float         g_Xg[(size_t)NVIS * N4D];        // 134 MB
__device__ __align__(128) __half g_h16[2 * NB * ND];      // double buffered h (fp16)
__device__ float         g_final[NB * ND];
__device__ unsigned      g_arrive;

// ---------------- helpers ----------------
__device__ __forceinline__ void mma_bf16(float* c, const unsigned* a, const unsigned* b) {
    asm volatile(
        "mma.sync.aligned.m16n8k16.row.col.f32.bf16.bf16.f32 "
        "{%0,%1,%2,%3}, {%4,%5,%6,%7}, {%8,%9}, {%0,%1,%2,%3};\n"
        : "+f"(c[0]), "+f"(c[1]), "+f"(c[2]), "+f"(c[3])
        : "r"(a[0]), "r"(a[1]), "r"(a[2]), "r"(a[3]), "r"(b[0]), "r"(b[1]));
}
__device__ __forceinline__ void mma_f16(float* c, const unsigned* a, const unsigned* b) {
    asm volatile(
        "mma.sync.aligned.m16n8k16.row.col.f32.f16.f16.f32 "
        "{%0,%1,%2,%3}, {%4,%5,%6,%7}, {%8,%9}, {%0,%1,%2,%3};\n"
        : "+f"(c[0]), "+f"(c[1]), "+f"(c[2]), "+f"(c[3])
        : "r"(a[0]), "r"(a[1]), "r"(a[2]), "r"(a[3]), "r"(b[0]), "r"(b[1]));
}

__device__ __forceinline__ void ldsm4(unsigned* r, unsigned saddr) {
    asm volatile("ldmatrix.sync.aligned.m8n8.x4.shared.b16 {%0,%1,%2,%3}, [%4];"
                 : "=r"(r[0]), "=r"(r[1]), "=r"(r[2]), "=r"(r[3]) : "r"(saddr));
}
__device__ __forceinline__ void ldsm2(unsigned* r, unsigned saddr) {
    asm volatile("ldmatrix.sync.aligned.m8n8.x2.shared.b16 {%0,%1}, [%2];"
                 : "=r"(r[0]), "=r"(r[1]) : "r"(saddr));
}
__device__ __forceinline__ void cp16(unsigned s, const void* g) {
    asm volatile("cp.async.cg.shared.global [%0], [%1], 16;\n" :: "r"(s), "l"(g));
}
__device__ __forceinline__ void cp_commit() {
    asm volatile("cp.async.commit_group;\n" ::: "memory");
}
template<int N> __device__ __forceinline__ void cp_wait() {
    asm volatile("cp.async.wait_group %0;\n" :: "n"(N) : "memory");
}

__device__ __forceinline__ void arrive_release(unsigned* p) {
    asm volatile("red.release.gpu.global.add.u32 [%0], 1;" :: "l"(p) : "memory");
}
__device__ __forceinline__ unsigned ld_acquire(const unsigned* p) {
    unsigned v;
    asm volatile("ld.acquire.gpu.global.u32 %0, [%1];" : "=r"(v) : "l"(p) : "memory");
    return v;
}

__device__ __forceinline__ void split_bf16(float v, __nv_bfloat16& hi, __nv_bfloat16& lo) {
    hi = __float2bfloat16_rn(v);
    lo = __float2bfloat16_rn(v - __bfloat162float(hi));
}
__device__ __forceinline__ void split_f16(float v, __half& hi, __half& lo) {
    hi = __float2half_rn(v);
    lo = __float2half_rn(v - __half2float(hi));
}

__device__ __forceinline__ float sigf(float x) {
    float e = __expf(-x);
    return __fdividef(1.f, 1.f + e);
}
__device__ __forceinline__ float tanhfast(float x) {
    float e = __expf(-2.f * fabsf(x));
    float r = __fdividef(1.f - e, 1.f + e);
    return copysignf(r, x);
}

// ---------------- kernel 1: weight prep ----------------
// W_ih -> bf16 hi/lo (for input GEMM), W_hh -> fp16 hi/lo (for recurrence)
__global__ void prep_weights(const float* __restrict__ wih, const float* __restrict__ whh) {
    int i = blockIdx.x * 256 + threadIdx.x;
    if (i < N4D * ND) {
        split_bf16(wih[i], g_Wih_hi[i], g_Wih_lo[i]);
        split_f16(whh[i], g_Wh16hi[i], g_Wh16lo[i]);
    }
}

// ---------------- kernel 2: embedding-bag sum -> X (hi/lo bf16) ----------------
__global__ void embed_kernel(const int* __restrict__ seqs, const float* __restrict__ emb) {
    int vis = blockIdx.x;          // 0..16383
    int t   = threadIdx.x;         // 0..127
    const int* s = seqs + vis * NC;
    float a0 = 0.f, a1 = 0.f, a2 = 0.f, a3 = 0.f;
#pragma unroll
    for (int c = 0; c < NC; c++) {
        int idx = s[c];
        if (idx >= VOCABI) continue;          // padding row -> zero
        const float* row = emb + (size_t)idx * ND;
        a0 += row[t];
        a1 += row[t + 128];
        a2 += row[t + 256];
        a3 += row[t + 384];
    }
    int base = vis * ND + t;
    split_bf16(a0, g_Xhi[base],       g_Xlo[base]);
    split_bf16(a1, g_Xhi[base + 128], g_Xlo[base + 128]);
    split_bf16(a2, g_Xhi[base + 256], g_Xlo[base + 256]);
    split_bf16(a3, g_Xhi[base + 384], g_Xlo[base + 384]);
}

// ---------------- kernel 3: input GEMM  Xg = X @ W_ih^T ----------------
// CTA tile 128x128, 512 threads = 16 warps (4m x 4n), warp tile 32x32.
// 3-stage cp.async pipeline, K=32 per stage, ldmatrix operand loads.
__global__ void __launch_bounds__(512, 1) input_gemm() {
    extern __shared__ unsigned gsm[];
    unsigned sbase = (unsigned)__cvta_generic_to_shared(gsm);

    int t = threadIdx.x;
    int w = t >> 5, lane = t & 31;
    int wm = w >> 2, wn = w & 3;
    int g = lane >> 2, q = lane & 3;
    int m0 = blockIdx.y * 128, n0 = blockIdx.x * 128;

    int lrow = t >> 2;             // 0..127
    int lch  = t & 3;              // 16B chunk

    const __nv_bfloat16* pAh = g_Xhi    + (size_t)(m0 + lrow) * ND + lch * 8;
    const __nv_bfloat16* pAl = g_Xlo    + (size_t)(m0 + lrow) * ND + lch * 8;
    const __nv_bfloat16* pBh = g_Wih_hi + (size_t)(n0 + lrow) * ND + lch * 8;
    const __nv_bfloat16* pBl = g_Wih_lo + (size_t)(n0 + lrow) * ND + lch * 8;
    unsigned sdst = sbase + lrow * GAST_B + lch * 16;

    float acc[2][4][4];
#pragma unroll
    for (int i = 0; i < 2; i++)
#pragma unroll
        for (int j = 0; j < 4; j++)
#pragma unroll
            for (int k = 0; k < 4; k++) acc[i][j][k] = 0.f;

    // prologue: stage 0 and 1
#pragma unroll
    for (int ps = 0; ps < 2; ps++) {
        unsigned d = sdst + ps * GSTAGE_B;
        const int ko = ps * 32;
        cp16(d,              pAh + ko);
        cp16(d + GARR_B,     pAl + ko);
        cp16(d + 2 * GARR_B, pBh + ko);
        cp16(d + 3 * GARR_B, pBl + ko);
        cp_commit();
    }

    // ldmatrix lane address components
    int arow = wm * 32 + (lane & 15);
    int acol = (lane >> 4) * 16;            // byte offset within k-chunk
    int brow = wn * 32 + (lane & 7) + (lane >> 4) * 8;
    int bcol = ((lane >> 3) & 1) * 16;

    int buf = 0;                   // = s % 3
    int nbuf = 2;                  // = (s+2) % 3
    for (int s = 0; s < 16; s++) {
        cp_wait<1>();              // group s complete (s+1 may pend)
        __syncthreads();           // all threads done reading buf (s-1)%3
        if (s + 2 < 16) {
            unsigned d = sdst + nbuf * GSTAGE_B;
            const int ko = (s + 2) * 32;
            cp16(d,              pAh + ko);
            cp16(d + GARR_B,     pAl + ko);
            cp16(d + 2 * GARR_B, pBh + ko);
            cp16(d + 3 * GARR_B, pBl + ko);
            cp_commit();
        }
        unsigned base = sbase + buf * GSTAGE_B;
#pragma unroll
        for (int kk = 0; kk < 2; kk++) {
            unsigned koff = kk * 32;
            unsigned ah[2][4], al[2][4], bh[2][4], bl[2][4];
#pragma unroll
            for (int i = 0; i < 2; i++) {
                unsigned ad = base + (arow + i * 16) * GAST_B + koff + acol;
                ldsm4(ah[i], ad);
                ldsm4(al[i], ad + GARR_B);
            }
#pragma unroll
            for (int j2 = 0; j2 < 2; j2++) {
                unsigned bd = base + 2 * GARR_B + (brow + j2 * 16) * GAST_B + koff + bcol;
                ldsm4(bh[j2], bd);
                ldsm4(bl[j2], bd + GARR_B);
            }
#pragma unroll
            for (int i = 0; i < 2; i++)
#pragma unroll
                for (int j = 0; j < 4; j++) {
                    unsigned bhf[2] = { bh[j >> 1][(j & 1) * 2], bh[j >> 1][(j & 1) * 2 + 1] };
                    unsigned blf[2] = { bl[j >> 1][(j & 1) * 2], bl[j >> 1][(j & 1) * 2 + 1] };
                    mma_bf16(acc[i][j], ah[i], bhf);
                    mma_bf16(acc[i][j], ah[i], blf);
                    mma_bf16(acc[i][j], al[i], bhf);
                }
        }
        buf = (buf == 2) ? 0 : buf + 1;
        nbuf = (nbuf == 2) ? 0 : nbuf + 1;
    }

#pragma unroll
    for (int i = 0; i < 2; i++) {
        int r0 = m0 + wm * 32 + i * 16 + g;
#pragma unroll
        for (int j = 0; j < 4; j++) {
            int cc = n0 + wn * 32 + j * 8 + 2 * q;
            *(float2*)(g_Xg + (size_t)r0 * N4D + cc)       = make_float2(acc[i][j][0], acc[i][j][1]);
            *(float2*)(g_Xg + (size_t)(r0 + 8) * N4D + cc) = make_float2(acc[i][j][2], acc[i][j][3]);
        }
    }
}

// ---------------- kernel 4: reset state + barrier ----------------
__global__ void reset_kernel() {
    int i = blockIdx.x * 256 + threadIdx.x;
    if (i < 2 * NB * ND / 2) {
        ((unsigned*)g_h16)[i] = 0u;
    }
    if (i == 0) g_arrive = 0u;
}

// ---------------- kernel 5: persistent LSTM recurrence ----------------
// 128 CTAs (1/SM), 256 threads. Each CTA owns 4 units (16 gate rows).
// W_hh slice (fp16 hi/lo) in SMEM all 256 steps. h (fp16 single) double-
// buffered in GMEM, staged per step in 4 K-chunks of cp.async overlapped
// with the mma consumption (2 fp16 mma per k-chunk).
__global__ void __launch_bounds__(256, 1) lstm_rec(const int* __restrict__ lengths) {
    extern __shared__ unsigned smem[];
    char* smc = (char*)smem;
    unsigned* sWh = (unsigned*)(smc + SM_W);            // GROWS*WSTRIDE u32 (hi), then lo
    unsigned* sWl = sWh + GROWS * WSTRIDE;
    float*  sG = (float*)(smc + SM_G);                  // NB * GSTRIDE

    unsigned sb = (unsigned)__cvta_generic_to_shared(smc);
    unsigned sWh_b = sb + SM_W;
    unsigned sH_b  = sb + SM_H;

    int t = threadIdx.x, cta = blockIdx.x;
    int w = t >> 5, lane = t & 31;
    int wm = w >> 1, wn = w & 1;
    int g = lane >> 2, q = lane & 3;

    // load W_hh slice into smem (fp16 hi/lo). slot s: u=s>>2, gate=s&3.
    const unsigned* Whi = (const unsigned*)g_Wh16hi;
    const unsigned* Wlo = (const unsigned*)g_Wh16lo;
    for (int i = t; i < GROWS * 256; i += 256) {
        int s = i >> 8, kw = i & 255;
        int u = s >> 2, gate = s & 3;
        int grow = gate * ND + cta * UNITS + u;
        sWh[s * WSTRIDE + kw] = Whi[grow * 256 + kw];
        sWl[s * WSTRIDE + kw] = Wlo[grow * 256 + kw];
    }

    // epilogue ownership: one (batch, unit) pair per thread
    int bb = t >> 2, uu = t & 3;
    int len0 = lengths[bb] - 1;
    float cst = 0.f;
    int jglob = cta * UNITS + uu;

    // ldmatrix lane addresses
    unsigned aoff = sH_b + (unsigned)(wm * 16 + (lane & 15)) * (WSTRIDE * 4) + (lane >> 4) * 16;
    unsigned boff = sWh_b + (unsigned)(wn * 8 + (lane & 7)) * (WSTRIDE * 4) + ((lane >> 3) & 1) * 16;
    const unsigned WLO = GROWS * WSTRIDE * 4;    // byte offset sWh -> sWl

    // prefetch Xg for step 0
    size_t xb0 = ((size_t)bb * NS + 0) * N4D + jglob;
    float x0 = __ldcg(g_Xg + xb0);
    float x1 = __ldcg(g_Xg + xb0 + 512);
    float x2 = __ldcg(g_Xg + xb0 + 1024);
    float x3 = __ldcg(g_Xg + xb0 + 1536);

    __syncthreads();

    for (int step = 0; step < NS; step++) {
        int rd = step & 1;
        int wr = rd ^ 1;

        // ---- issue h staging: 4 K-chunks (256B per row each), one group each ----
        {
            const char* hsrc = (const char*)g_h16 + (size_t)rd * (NB * ND * 2);
#pragma unroll
            for (int c = 0; c < 4; c++) {
#pragma unroll
                for (int i = t; i < 1024; i += 256) {
                    int r = i >> 4, sg = i & 15;
                    unsigned dst = sH_b + (unsigned)r * (WSTRIDE * 4) + c * 256 + sg * 16;
                    cp16(dst, hsrc + (size_t)r * 1024 + c * 256 + sg * 16);
                }
                cp_commit();
            }
        }

        // ---- mma over 4 chunks, overlapped with staging ----
        float acc[4] = {0.f, 0.f, 0.f, 0.f};
#pragma unroll
        for (int c = 0; c < 4; c++) {
            if (c == 0) cp_wait<3>();
            else if (c == 1) cp_wait<2>();
            else if (c == 2) cp_wait<1>();
            else cp_wait<0>();
            __syncthreads();
#pragma unroll
            for (int j = 0; j < 8; j++) {
                int kc = c * 8 + j;
                unsigned ah[4], bh[2], bl[2];
                ldsm4(ah, aoff + kc * 32);
                ldsm2(bh, boff + kc * 32);
                ldsm2(bl, boff + kc * 32 + WLO);
                mma_f16(acc, ah, bh);
                mma_f16(acc, ah, bl);
            }
        }

        {
            int r0 = wm * 16 + g, c0 = wn * 8 + 2 * q;
            *(float2*)(sG + r0 * GSTRIDE + c0)       = make_float2(acc[0], acc[1]);
            *(float2*)(sG + (r0 + 8) * GSTRIDE + c0) = make_float2(acc[2], acc[3]);
        }
        __syncthreads();

        // ---- epilogue ----
        {
            const float* gp = sG + bb * GSTRIDE + uu * 4;
            float gi = gp[0] + x0;
            float gf = gp[1] + x1;
            float gg = gp[2] + x2;
            float go = gp[3] + x3;
            float iv = sigf(gi);
            float fv = sigf(gf);
            float gv = tanhfast(gg);
            float ov = sigf(go);
            float c = fv * cst + iv * gv;
            cst = c;
            float hv = ov * tanhfast(c);
            g_h16[wr * (NB * ND) + bb * ND + jglob] = __float2half_rn(hv);
            if (step == len0) g_final[bb * ND + jglob] = hv;
        }
        __syncthreads();            // all h writes issued (+ sG reads done)

        // ---- arrive ----
        if (t == 0) arrive_release(&g_arrive);

        // ---- prefetch next step's Xg while barrier settles ----
        {
            int nstep = (step + 1 < NS) ? step + 1 : 0;
            size_t xb = ((size_t)bb * NS + nstep) * N4D + jglob;
            x0 = __ldcg(g_Xg + xb);
            x1 = __ldcg(g_Xg + xb + 512);
            x2 = __ldcg(g_Xg + xb + 1024);
            x3 = __ldcg(g_Xg + xb + 1536);
        }

        // ---- wait ----
        if (t == 0) {
            unsigned target = (unsigned)NCTA_REC * (unsigned)(step + 1);
            while (ld_acquire(&g_arrive) < target) { }
        }
        __syncthreads();
    }
}

// ---------------- kernel 6: output projection ----------------
__global__ void final_out(const float* __restrict__ w_out, const float* __restrict__ b_out,
                          float* __restrict__ out) {
    int b = blockIdx.x;
    int t = threadIdx.x;
    int r = t >> 5, lane = t & 31;
    float s = 0.f;
    for (int k = lane; k < ND; k += 32)
        s += g_final[b * ND + k] * w_out[r * ND + k];
#pragma unroll
    for (int off = 16; off; off >>= 1) s += __shfl_down_sync(0xffffffffu, s, off);
    if (lane == 0) out[b * 2 + r] = s + b_out[r];
}

// ---------------- launch ----------------
extern "C" void kernel_launch(void* const* d_in, const int* in_sizes, int n_in,
                              void* d_out, int out_size) {
    const int*   seqs    = (const int*)d_in[0];
    const int*   lengths = (const int*)d_in[1];
    const float* emb     = (const float*)d_in[2];
    const float* wih     = (const float*)d_in[3];
    const float* whh     = (const float*)d_in[4];
    const float* wout    = (const float*)d_in[5];
    const float* bout    = (const float*)d_in[6];
    float* out = (float*)d_out;

    cudaFuncSetAttribute(lstm_rec, cudaFuncAttributeMaxDynamicSharedMemorySize, SM_TOT);
    const int gemm_smem = GNSTAGE * GSTAGE_B;
    cudaFuncSetAttribute(input_gemm, cudaFuncAttributeMaxDynamicSharedMemorySize, gemm_smem);

    prep_weights<<<4096, 256>>>(wih, whh);
    embed_kernel<<<NVIS, 128>>>(seqs, emb);
    dim3 gg(N4D / 128, NVIS / 128);
    input_gemm<<<gg, 512, gemm_smem>>>();
    reset_kernel<<<128, 256>>>();
    lstm_rec<<<NCTA_REC, 256, SM_TOT>>>(lengths);
    final_out<<<NB, 64>>>(wout, bout, out);
}

// round 8
// speedup vs baseline: 2.0418x; 1.2178x over previous
#include <cuda_runtime.h>
#include <cuda_bf16.h>
#include <cuda_fp16.h>
#include <math.h>

// Problem sizes
#define NB    64
#define NS    256
#define NC    16
#define ND    512
#define N4D   2048
#define NVIS  16384            // NB*NS
#define VOCABI 20000

// Recurrence config: 4 batch-groups x 32 unit-groups = 128 CTAs (1/SM)
#define NCTA_REC 128
#define BGRPS    4
#define BPC      16            // batches per CTA
#define UNITS    16            // hidden units per CTA
#define GROWS    64            // gate rows per CTA (UNITS*4)
#define NGRP     32            // CTAs per batch group
#define WSTRIDE  260           // u32 stride for a 512-half row (+16B pad) = 1040 B
#define GST2     68            // float stride for gates smem rows (64 + 4 pad)

// lstm_rec smem byte offsets
#define SM_W    0
#define SM_WSZ  (GROWS * WSTRIDE * 4)               // 66560 (W fp16 single)
#define SM_H    SM_WSZ                              // 66560
#define SM_HSZ  (BPC * WSTRIDE * 4)                 // 16640
#define SM_G    (SM_H + SM_HSZ)                     // 83200
#define SM_TOT  (SM_G + BPC * GST2 * 4)             // 87552

// GEMM config
#define GAST_B   80            // bytes per smem row (32 bf16 + 8 pad)
#define GARR_B   10240         // bytes per array per stage (128 rows * 80)
#define GSTAGE_B 40960         // 4 arrays
#define GNSTAGE  3

// ---------------- device scratch (static globals: no allocation) ----------------
__device__ __nv_bfloat16 g_Xhi[NVIS * ND];
__device__ __nv_bfloat16 g_Xlo[NVIS * ND];
__device__ __nv_bfloat16 g_Wih_hi[N4D * ND];
__device__ __nv_bfloat16 g_Wih_lo[N4D * ND];
__device__ __half        g_Wh16[N4D * ND];
__device__ float         g_Xg[(size_t)NVIS * N4D];        // 134 MB
__device__ __align__(128) __half g_h16[2 * NB * ND];      // double buffered h (fp16)
__device__ float         g_final[NB * ND];
__device__ unsigned      g_arr[BGRPS * 32];               // 4 counters, 128B apart

// ---------------- helpers ----------------
__device__ __forceinline__ void mma_bf16(float* c, const unsigned* a, const unsigned* b) {
    asm volatile(
        "mma.sync.aligned.m16n8k16.row.col.f32.bf16.bf16.f32 "
        "{%0,%1,%2,%3}, {%4,%5,%6,%7}, {%8,%9}, {%0,%1,%2,%3};\n"
        : "+f"(c[0]), "+f"(c[1]), "+f"(c[2]), "+f"(c[3])
        : "r"(a[0]), "r"(a[1]), "r"(a[2]), "r"(a[3]), "r"(b[0]), "r"(b[1]));
}
__device__ __forceinline__ void mma_f16(float* c, const unsigned* a, const unsigned* b) {
    asm volatile(
        "mma.sync.aligned.m16n8k16.row.col.f32.f16.f16.f32 "
        "{%0,%1,%2,%3}, {%4,%5,%6,%7}, {%8,%9}, {%0,%1,%2,%3};\n"
        : "+f"(c[0]), "+f"(c[1]), "+f"(c[2]), "+f"(c[3])
        : "r"(a[0]), "r"(a[1]), "r"(a[2]), "r"(a[3]), "r"(b[0]), "r"(b[1]));
}

__device__ __forceinline__ void ldsm4(unsigned* r, unsigned saddr) {
    asm volatile("ldmatrix.sync.aligned.m8n8.x4.shared.b16 {%0,%1,%2,%3}, [%4];"
                 : "=r"(r[0]), "=r"(r[1]), "=r"(r[2]), "=r"(r[3]) : "r"(saddr));
}
__device__ __forceinline__ void ldsm2(unsigned* r, unsigned saddr) {
    asm volatile("ldmatrix.sync.aligned.m8n8.x2.shared.b16 {%0,%1}, [%2];"
                 : "=r"(r[0]), "=r"(r[1]) : "r"(saddr));
}
__device__ __forceinline__ void cp16(unsigned s, const void* g) {
    asm volatile("cp.async.cg.shared.global [%0], [%1], 16;\n" :: "r"(s), "l"(g));
}
__device__ __forceinline__ void cp_commit() {
    asm volatile("cp.async.commit_group;\n" ::: "memory");
}
template<int N> __device__ __forceinline__ void cp_wait() {
    asm volatile("cp.async.wait_group %0;\n" :: "n"(N) : "memory");
}

__device__ __forceinline__ void arrive_release(unsigned* p) {
    asm volatile("red.release.gpu.global.add.u32 [%0], 1;" :: "l"(p) : "memory");
}
__device__ __forceinline__ unsigned ld_acquire(const unsigned* p) {
    unsigned v;
    asm volatile("ld.acquire.gpu.global.u32 %0, [%1];" : "=r"(v) : "l"(p) : "memory");
    return v;
}

__device__ __forceinline__ void split_bf16(float v, __nv_bfloat16& hi, __nv_bfloat16& lo) {
    hi = __float2bfloat16_rn(v);
    lo = __float2bfloat16_rn(v - __bfloat162float(hi));
}

__device__ __forceinline__ float sigf(float x) {
    float e = __expf(-x);
    return __fdividef(1.f, 1.f + e);
}
__device__ __forceinline__ float tanhfast(float x) {
    float e = __expf(-2.f * fabsf(x));
    float r = __fdividef(1.f - e, 1.f + e);
    return copysignf(r, x);
}

// ---------------- kernel 1: weight prep ----------------
// W_ih -> bf16 hi/lo (input GEMM); W_hh -> fp16 single (recurrence)
__global__ void prep_weights(const float* __restrict__ wih, const float* __restrict__ whh) {
    int i = blockIdx.x * 256 + threadIdx.x;
    if (i < N4D * ND) {
        split_bf16(wih[i], g_Wih_hi[i], g_Wih_lo[i]);
        g_Wh16[i] = __float2half_rn(whh[i]);
    }
}

// ---------------- kernel 2: embedding-bag sum -> X (hi/lo bf16) ----------------
__global__ void embed_kernel(const int* __restrict__ seqs, const float* __restrict__ emb) {
    int vis = blockIdx.x;          // 0..16383
    int t   = threadIdx.x;         // 0..127
    const int* s = seqs + vis * NC;
    float a0 = 0.f, a1 = 0.f, a2 = 0.f, a3 = 0.f;
#pragma unroll
    for (int c = 0; c < NC; c++) {
        int idx = s[c];
        if (idx >= VOCABI) continue;          // padding row -> zero
        const float* row = emb + (size_t)idx * ND;
        a0 += row[t];
        a1 += row[t + 128];
        a2 += row[t + 256];
        a3 += row[t + 384];
    }
    int base = vis * ND + t;
    split_bf16(a0, g_Xhi[base],       g_Xlo[base]);
    split_bf16(a1, g_Xhi[base + 128], g_Xlo[base + 128]);
    split_bf16(a2, g_Xhi[base + 256], g_Xlo[base + 256]);
    split_bf16(a3, g_Xhi[base + 384], g_Xlo[base + 384]);
}

// ---------------- kernel 3: input GEMM  Xg = X @ W_ih^T ----------------
// CTA tile 128x128, 512 threads = 16 warps (4m x 4n), warp tile 32x32.
// 3-stage cp.async pipeline, K=32 per stage, ldmatrix operand loads.
__global__ void __launch_bounds__(512, 1) input_gemm() {
    extern __shared__ unsigned gsm[];
    unsigned sbase = (unsigned)__cvta_generic_to_shared(gsm);

    int t = threadIdx.x;
    int w = t >> 5, lane = t & 31;
    int wm = w >> 2, wn = w & 3;
    int g = lane >> 2, q = lane & 3;
    int m0 = blockIdx.y * 128, n0 = blockIdx.x * 128;

    int lrow = t >> 2;             // 0..127
    int lch  = t & 3;              // 16B chunk

    const __nv_bfloat16* pAh = g_Xhi    + (size_t)(m0 + lrow) * ND + lch * 8;
    const __nv_bfloat16* pAl = g_Xlo    + (size_t)(m0 + lrow) * ND + lch * 8;
    const __nv_bfloat16* pBh = g_Wih_hi + (size_t)(n0 + lrow) * ND + lch * 8;
    const __nv_bfloat16* pBl = g_Wih_lo + (size_t)(n0 + lrow) * ND + lch * 8;
    unsigned sdst = sbase + lrow * GAST_B + lch * 16;

    float acc[2][4][4];
#pragma unroll
    for (int i = 0; i < 2; i++)
#pragma unroll
        for (int j = 0; j < 4; j++)
#pragma unroll
            for (int k = 0; k < 4; k++) acc[i][j][k] = 0.f;

    // prologue: stage 0 and 1
#pragma unroll
    for (int ps = 0; ps < 2; ps++) {
        unsigned d = sdst + ps * GSTAGE_B;
        const int ko = ps * 32;
        cp16(d,              pAh + ko);
        cp16(d + GARR_B,     pAl + ko);
        cp16(d + 2 * GARR_B, pBh + ko);
        cp16(d + 3 * GARR_B, pBl + ko);
        cp_commit();
    }

    int arow = wm * 32 + (lane & 15);
    int acol = (lane >> 4) * 16;
    int brow = wn * 32 + (lane & 7) + (lane >> 4) * 8;
    int bcol = ((lane >> 3) & 1) * 16;

    int buf = 0, nbuf = 2;
    for (int s = 0; s < 16; s++) {
        cp_wait<1>();
        __syncthreads();
        if (s + 2 < 16) {
            unsigned d = sdst + nbuf * GSTAGE_B;
            const int ko = (s + 2) * 32;
            cp16(d,              pAh + ko);
            cp16(d + GARR_B,     pAl + ko);
            cp16(d + 2 * GARR_B, pBh + ko);
            cp16(d + 3 * GARR_B, pBl + ko);
            cp_commit();
        }
        unsigned base = sbase + buf * GSTAGE_B;
#pragma unroll
        for (int kk = 0; kk < 2; kk++) {
            unsigned koff = kk * 32;
            unsigned ah[2][4], al[2][4], bh[2][4], bl[2][4];
#pragma unroll
            for (int i = 0; i < 2; i++) {
                unsigned ad = base + (arow + i * 16) * GAST_B + koff + acol;
                ldsm4(ah[i], ad);
                ldsm4(al[i], ad + GARR_B);
            }
#pragma unroll
            for (int j2 = 0; j2 < 2; j2++) {
                unsigned bd = base + 2 * GARR_B + (brow + j2 * 16) * GAST_B + koff + bcol;
                ldsm4(bh[j2], bd);
                ldsm4(bl[j2], bd + GARR_B);
            }
#pragma unroll
            for (int i = 0; i < 2; i++)
#pragma unroll
                for (int j = 0; j < 4; j++) {
                    unsigned bhf[2] = { bh[j >> 1][(j & 1) * 2], bh[j >> 1][(j & 1) * 2 + 1] };
                    unsigned blf[2] = { bl[j >> 1][(j & 1) * 2], bl[j >> 1][(j & 1) * 2 + 1] };
                    mma_bf16(acc[i][j], ah[i], bhf);
                    mma_bf16(acc[i][j], ah[i], blf);
                    mma_bf16(acc[i][j], al[i], bhf);
                }
        }
        buf = (buf == 2) ? 0 : buf + 1;
        nbuf = (nbuf == 2) ? 0 : nbuf + 1;
    }

#pragma unroll
    for (int i = 0; i < 2; i++) {
        int r0 = m0 + wm * 32 + i * 16 + g;
#pragma unroll
        for (int j = 0; j < 4; j++) {
            int cc = n0 + wn * 32 + j * 8 + 2 * q;
            *(float2*)(g_Xg + (size_t)r0 * N4D + cc)       = make_float2(acc[i][j][0], acc[i][j][1]);
            *(float2*)(g_Xg + (size_t)(r0 + 8) * N4D + cc) = make_float2(acc[i][j][2], acc[i][j][3]);
        }
    }
}

// ---------------- kernel 4: reset state + barriers ----------------
__global__ void reset_kernel() {
    int i = blockIdx.x * 256 + threadIdx.x;
    if (i < 2 * NB * ND / 2) {
        ((unsigned*)g_h16)[i] = 0u;
    }
    if (i < BGRPS * 32) g_arr[i] = 0u;
}

// ---------------- kernel 5: persistent LSTM recurrence ----------------
// 128 CTAs (1/SM) = 4 batch-groups x 32 unit-groups, 256 threads each.
// CTA owns 16 batches x 16 units (64 gate rows). W_hh slice (fp16) lives in
// SMEM all 256 steps. h (fp16) double-buffered in GMEM; per step each CTA
// stages only its 16 batch rows (16 KB) in 4 K-chunks overlapped with mma.
// Grid barrier is per-batch-group (32 CTAs).
__global__ void __launch_bounds__(256, 1) lstm_rec(const int* __restrict__ lengths) {
    extern __shared__ unsigned smem[];
    char* smc = (char*)smem;
    unsigned* sW = (unsigned*)(smc + SM_W);             // GROWS*WSTRIDE u32
    float*  sG = (float*)(smc + SM_G);                  // BPC * GST2

    unsigned sb = (unsigned)__cvta_generic_to_shared(smc);
    unsigned sW_b = sb + SM_W;
    unsigned sH_b = sb + SM_H;

    int t = threadIdx.x, cta = blockIdx.x;
    int wn = t >> 5, lane = t & 31;           // 8 warps, all on N
    int g = lane >> 2, q = lane & 3;

    int bgrp = cta >> 5;            // 0..3
    int ugrp = cta & 31;            // 0..31
    int jbase = ugrp * UNITS;

    // load W_hh slice (fp16). slot s (0..63): u=s>>2, gate=s&3.
    const unsigned* Wsrc = (const unsigned*)g_Wh16;
    for (int i = t; i < GROWS * 256; i += 256) {
        int s = i >> 8, kw = i & 255;
        int u = s >> 2, gate = s & 3;
        int grow = gate * ND + jbase + u;
        sW[s * WSTRIDE + kw] = Wsrc[grow * 256 + kw];
    }

    // epilogue ownership: (batch, unit) per thread: 16 x 16 = 256
    int bloc = t >> 4, uu = t & 15;
    int b = bgrp * BPC + bloc;
    int len0 = lengths[b] - 1;
    float cst = 0.f;
    int jglob = jbase + uu;

    // ldmatrix lane addresses
    unsigned aoff = sH_b + (unsigned)(lane & 15) * (WSTRIDE * 4) + (lane >> 4) * 16;
    unsigned boff = sW_b + (unsigned)(wn * 8 + (lane & 7)) * (WSTRIDE * 4) + ((lane >> 3) & 1) * 16;

    // staging: 16 rows x 1024B, 4 chunks of 256B/row; 256 cp16/chunk (1/thread)
    int sr = t >> 4, ssg = t & 15;
    unsigned sdst0 = sH_b + (unsigned)sr * (WSTRIDE * 4) + ssg * 16;
    size_t ssrc0 = (size_t)sr * 1024 + ssg * 16;

    unsigned* arrp = &g_arr[bgrp * 32];

    // prefetch Xg for step 0
    size_t xb0 = ((size_t)b * NS + 0) * N4D + jglob;
    float x0 = __ldcg(g_Xg + xb0);
    float x1 = __ldcg(g_Xg + xb0 + 512);
    float x2 = __ldcg(g_Xg + xb0 + 1024);
    float x3 = __ldcg(g_Xg + xb0 + 1536);

    __syncthreads();

    for (int step = 0; step < NS; step++) {
        int rd = step & 1;
        int wr = rd ^ 1;

        // ---- issue h staging: 4 K-chunks, one commit group each ----
        {
            const char* hsrc = (const char*)g_h16 + (size_t)rd * (NB * ND * 2)
                             + (size_t)bgrp * (BPC * 1024);
#pragma unroll
            for (int c = 0; c < 4; c++) {
                cp16(sdst0 + c * 256, hsrc + ssrc0 + c * 256);
                cp_commit();
            }
        }

        // ---- mma over 4 chunks, overlapped with staging ----
        float acc[4] = {0.f, 0.f, 0.f, 0.f};
#pragma unroll
        for (int c = 0; c < 4; c++) {
            if (c == 0) cp_wait<3>();
            else if (c == 1) cp_wait<2>();
            else if (c == 2) cp_wait<1>();
            else cp_wait<0>();
            __syncthreads();
#pragma unroll
            for (int j = 0; j < 8; j++) {
                int kc = c * 8 + j;
                unsigned ah[4], bw[2];
                ldsm4(ah, aoff + kc * 32);
                ldsm2(bw, boff + kc * 32);
                mma_f16(acc, ah, bw);
            }
        }

        {
            int c0 = wn * 8 + 2 * q;
            *(float2*)(sG + g * GST2 + c0)       = make_float2(acc[0], acc[1]);
            *(float2*)(sG + (g + 8) * GST2 + c0) = make_float2(acc[2], acc[3]);
        }
        __syncthreads();

        // ---- epilogue ----
        {
            const float* gp = sG + bloc * GST2 + uu * 4;
            float gi = gp[0] + x0;
            float gf = gp[1] + x1;
            float gg = gp[2] + x2;
            float go = gp[3] + x3;
            float iv = sigf(gi);
            float fv = sigf(gf);
            float gv = tanhfast(gg);
            float ov = sigf(go);
            float c = fv * cst + iv * gv;
            cst = c;
            float hv = ov * tanhfast(c);
            g_h16[wr * (NB * ND) + b * ND + jglob] = __float2half_rn(hv);
            if (step == len0) g_final[b * ND + jglob] = hv;
        }
        __syncthreads();            // all h writes issued (+ sG reads done)

        // ---- arrive (group barrier) ----
        if (t == 0) arrive_release(arrp);

        // ---- prefetch next step's Xg while barrier settles ----
        {
            int nstep = (step + 1 < NS) ? step + 1 : 0;
            size_t xb = ((size_t)b * NS + nstep) * N4D + jglob;
            x0 = __ldcg(g_Xg + xb);
            x1 = __ldcg(g_Xg + xb + 512);
            x2 = __ldcg(g_Xg + xb + 1024);
            x3 = __ldcg(g_Xg + xb + 1536);
        }

        // ---- wait (32 CTAs of this batch group) ----
        if (t == 0) {
            unsigned target = (unsigned)NGRP * (unsigned)(step + 1);
            while (ld_acquire(arrp) < target) { }
        }
        __syncthreads();
    }
}

// ---------------- kernel 6: output projection ----------------
__global__ void final_out(const float* __restrict__ w_out, const float* __restrict__ b_out,
                          float* __restrict__ out) {
    int b = blockIdx.x;
    int t = threadIdx.x;
    int r = t >> 5, lane = t & 31;
    float s = 0.f;
    for (int k = lane; k < ND; k += 32)
        s += g_final[b * ND + k] * w_out[r * ND + k];
#pragma unroll
    for (int off = 16; off; off >>= 1) s += __shfl_down_sync(0xffffffffu, s, off);
    if (lane == 0) out[b * 2 + r] = s + b_out[r];
}

// ---------------- launch ----------------
extern "C" void kernel_launch(void* const* d_in, const int* in_sizes, int n_in,
                              void* d_out, int out_size) {
    const int*   seqs    = (const int*)d_in[0];
    const int*   lengths = (const int*)d_in[1];
    const float* emb     = (const float*)d_in[2];
    const float* wih     = (const float*)d_in[3];
    const float* whh     = (const float*)d_in[4];
    const float* wout    = (const float*)d_in[5];
    const float* bout    = (const float*)d_in[6];
    float* out = (float*)d_out;

    cudaFuncSetAttribute(lstm_rec, cudaFuncAttributeMaxDynamicSharedMemorySize, SM_TOT);
    const int gemm_smem = GNSTAGE * GSTAGE_B;
    cudaFuncSetAttribute(input_gemm, cudaFuncAttributeMaxDynamicSharedMemorySize, gemm_smem);

    prep_weights<<<4096, 256>>>(wih, whh);
    embed_kernel<<<NVIS, 128>>>(seqs, emb);
    dim3 gg(N4D / 128, NVIS / 128);
    input_gemm<<<gg, 512, gemm_smem>>>();
    reset_kernel<<<128, 256>>>();
    lstm_rec<<<NCTA_REC, 256, SM_TOT>>>(lengths);
    final_out<<<NB, 64>>>(wout, bout, out);
}

// round 9
// speedup vs baseline: 2.1555x; 1.0557x over previous
#include <cuda_runtime.h>
#include <cuda_bf16.h>
#include <cuda_fp16.h>
#include <math.h>

// Problem sizes
#define NB    64
#define NS    256
#define NC    16
#define ND    512
#define N4D   2048
#define NVIS  16384            // NB*NS
#define VOCABI 20000

// Recurrence config: 4 batch-groups x 32 unit-groups = 128 CTAs (1/SM)
#define NCTA_REC 128
#define BGRPS    4
#define BPC      16            // batches per CTA
#define UNITS    16            // hidden units per CTA
#define GROWS    64            // gate rows per CTA (UNITS*4)
#define NGRP     32            // CTAs per batch group
#define WSTRIDE  260           // u32 stride for a 512-half row (+16B pad) = 1040 B

// lstm_rec smem byte offsets
#define SM_W    0
#define SM_WSZ  (GROWS * WSTRIDE * 4)               // 66560 (W fp16 single)
#define SM_H    SM_WSZ                              // 66560
#define SM_HSZ  (BPC * WSTRIDE * 4)                 // 16640
#define SM_TOT  (SM_H + SM_HSZ)                     // 83200

// GEMM config
#define GAST_B   80            // bytes per smem row (32 bf16 + 8 pad)
#define GARR_B   10240         // bytes per array per stage (128 rows * 80)
#define GSTAGE_B 40960         // 4 arrays
#define GNSTAGE  3

// ---------------- device scratch (static globals: no allocation) ----------------
__device__ __nv_bfloat16 g_Xhi[NVIS * ND];
__device__ __nv_bfloat16 g_Xlo[NVIS * ND];
__device__ __nv_bfloat16 g_Wih_hi[N4D * ND];
__device__ __nv_bfloat16 g_Wih_lo[N4D * ND];
__device__ __half        g_Wh16[N4D * ND];
__device__ float         g_Xg[(size_t)NVIS * N4D];        // 134 MB
__device__ __align__(128) __half g_h16[2 * NB * ND];      // double buffered h (fp16)
__device__ float         g_final[NB * ND];
__device__ unsigned      g_arr[BGRPS * 32];               // 4 counters, 128B apart

// ---------------- helpers ----------------
__device__ __forceinline__ void mma_bf16(float* c, const unsigned* a, const unsigned* b) {
    asm volatile(
        "mma.sync.aligned.m16n8k16.row.col.f32.bf16.bf16.f32 "
        "{%0,%1,%2,%3}, {%4,%5,%6,%7}, {%8,%9}, {%0,%1,%2,%3};\n"
        : "+f"(c[0]), "+f"(c[1]), "+f"(c[2]), "+f"(c[3])
        : "r"(a[0]), "r"(a[1]), "r"(a[2]), "r"(a[3]), "r"(b[0]), "r"(b[1]));
}
__device__ __forceinline__ void mma_f16(float* c, const unsigned* a, const unsigned* b) {
    asm volatile(
        "mma.sync.aligned.m16n8k16.row.col.f32.f16.f16.f32 "
        "{%0,%1,%2,%3}, {%4,%5,%6,%7}, {%8,%9}, {%0,%1,%2,%3};\n"
        : "+f"(c[0]), "+f"(c[1]), "+f"(c[2]), "+f"(c[3])
        : "r"(a[0]), "r"(a[1]), "r"(a[2]), "r"(a[3]), "r"(b[0]), "r"(b[1]));
}

__device__ __forceinline__ void ldsm4(unsigned* r, unsigned saddr) {
    asm volatile("ldmatrix.sync.aligned.m8n8.x4.shared.b16 {%0,%1,%2,%3}, [%4];"
                 : "=r"(r[0]), "=r"(r[1]), "=r"(r[2]), "=r"(r[3]) : "r"(saddr));
}
__device__ __forceinline__ void ldsm2(unsigned* r, unsigned saddr) {
    asm volatile("ldmatrix.sync.aligned.m8n8.x2.shared.b16 {%0,%1}, [%2];"
                 : "=r"(r[0]), "=r"(r[1]) : "r"(saddr));
}
__device__ __forceinline__ void cp16(unsigned s, const void* g) {
    asm volatile("cp.async.cg.shared.global [%0], [%1], 16;\n" :: "r"(s), "l"(g));
}
__device__ __forceinline__ void cp_commit() {
    asm volatile("cp.async.commit_group;\n" ::: "memory");
}
template<int N> __device__ __forceinline__ void cp_wait() {
    asm volatile("cp.async.wait_group %0;\n" :: "n"(N) : "memory");
}

__device__ __forceinline__ void arrive_release(unsigned* p) {
    asm volatile("red.release.gpu.global.add.u32 [%0], 1;" :: "l"(p) : "memory");
}
__device__ __forceinline__ unsigned ld_acquire(const unsigned* p) {
    unsigned v;
    asm volatile("ld.acquire.gpu.global.u32 %0, [%1];" : "=r"(v) : "l"(p) : "memory");
    return v;
}

__device__ __forceinline__ void split_bf16(float v, __nv_bfloat16& hi, __nv_bfloat16& lo) {
    hi = __float2bfloat16_rn(v);
    lo = __float2bfloat16_rn(v - __bfloat162float(hi));
}

__device__ __forceinline__ float sigf(float x) {
    float e = __expf(-x);
    return __fdividef(1.f, 1.f + e);
}
__device__ __forceinline__ float tanhfast(float x) {
    float e = __expf(-2.f * fabsf(x));
    float r = __fdividef(1.f - e, 1.f + e);
    return copysignf(r, x);
}

// ---------------- kernel 1: weight prep ----------------
__global__ void prep_weights(const float* __restrict__ wih, const float* __restrict__ whh) {
    int i = blockIdx.x * 256 + threadIdx.x;
    if (i < N4D * ND) {
        split_bf16(wih[i], g_Wih_hi[i], g_Wih_lo[i]);
        g_Wh16[i] = __float2half_rn(whh[i]);
    }
}

// ---------------- kernel 2: embedding-bag sum -> X (hi/lo bf16) ----------------
__global__ void embed_kernel(const int* __restrict__ seqs, const float* __restrict__ emb) {
    int vis = blockIdx.x;          // 0..16383
    int t   = threadIdx.x;         // 0..127
    const int* s = seqs + vis * NC;
    float a0 = 0.f, a1 = 0.f, a2 = 0.f, a3 = 0.f;
#pragma unroll
    for (int c = 0; c < NC; c++) {
        int idx = s[c];
        if (idx >= VOCABI) continue;          // padding row -> zero
        const float* row = emb + (size_t)idx * ND;
        a0 += row[t];
        a1 += row[t + 128];
        a2 += row[t + 256];
        a3 += row[t + 384];
    }
    int base = vis * ND + t;
    split_bf16(a0, g_Xhi[base],       g_Xlo[base]);
    split_bf16(a1, g_Xhi[base + 128], g_Xlo[base + 128]);
    split_bf16(a2, g_Xhi[base + 256], g_Xlo[base + 256]);
    split_bf16(a3, g_Xhi[base + 384], g_Xlo[base + 384]);
}

// ---------------- kernel 3: input GEMM  Xg = X @ W_ih^T ----------------
__global__ void __launch_bounds__(512, 1) input_gemm() {
    extern __shared__ unsigned gsm[];
    unsigned sbase = (unsigned)__cvta_generic_to_shared(gsm);

    int t = threadIdx.x;
    int w = t >> 5, lane = t & 31;
    int wm = w >> 2, wn = w & 3;
    int g = lane >> 2, q = lane & 3;
    int m0 = blockIdx.y * 128, n0 = blockIdx.x * 128;

    int lrow = t >> 2;             // 0..127
    int lch  = t & 3;              // 16B chunk

    const __nv_bfloat16* pAh = g_Xhi    + (size_t)(m0 + lrow) * ND + lch * 8;
    const __nv_bfloat16* pAl = g_Xlo    + (size_t)(m0 + lrow) * ND + lch * 8;
    const __nv_bfloat16* pBh = g_Wih_hi + (size_t)(n0 + lrow) * ND + lch * 8;
    const __nv_bfloat16* pBl = g_Wih_lo + (size_t)(n0 + lrow) * ND + lch * 8;
    unsigned sdst = sbase + lrow * GAST_B + lch * 16;

    float acc[2][4][4];
#pragma unroll
    for (int i = 0; i < 2; i++)
#pragma unroll
        for (int j = 0; j < 4; j++)
#pragma unroll
            for (int k = 0; k < 4; k++) acc[i][j][k] = 0.f;

#pragma unroll
    for (int ps = 0; ps < 2; ps++) {
        unsigned d = sdst + ps * GSTAGE_B;
        const int ko = ps * 32;
        cp16(d,              pAh + ko);
        cp16(d + GARR_B,     pAl + ko);
        cp16(d + 2 * GARR_B, pBh + ko);
        cp16(d + 3 * GARR_B, pBl + ko);
        cp_commit();
    }

    int arow = wm * 32 + (lane & 15);
    int acol = (lane >> 4) * 16;
    int brow = wn * 32 + (lane & 7) + (lane >> 4) * 8;
    int bcol = ((lane >> 3) & 1) * 16;

    int buf = 0, nbuf = 2;
    for (int s = 0; s < 16; s++) {
        cp_wait<1>();
        __syncthreads();
        if (s + 2 < 16) {
            unsigned d = sdst + nbuf * GSTAGE_B;
            const int ko = (s + 2) * 32;
            cp16(d,              pAh + ko);
            cp16(d + GARR_B,     pAl + ko);
            cp16(d + 2 * GARR_B, pBh + ko);
            cp16(d + 3 * GARR_B, pBl + ko);
            cp_commit();
        }
        unsigned base = sbase + buf * GSTAGE_B;
#pragma unroll
        for (int kk = 0; kk < 2; kk++) {
            unsigned koff = kk * 32;
            unsigned ah[2][4], al[2][4], bh[2][4], bl[2][4];
#pragma unroll
            for (int i = 0; i < 2; i++) {
                unsigned ad = base + (arow + i * 16) * GAST_B + koff + acol;
                ldsm4(ah[i], ad);
                ldsm4(al[i], ad + GARR_B);
            }
#pragma unroll
            for (int j2 = 0; j2 < 2; j2++) {
                unsigned bd = base + 2 * GARR_B + (brow + j2 * 16) * GAST_B + koff + bcol;
                ldsm4(bh[j2], bd);
                ldsm4(bl[j2], bd + GARR_B);
            }
#pragma unroll
            for (int i = 0; i < 2; i++)
#pragma unroll
                for (int j = 0; j < 4; j++) {
                    unsigned bhf[2] = { bh[j >> 1][(j & 1) * 2], bh[j >> 1][(j & 1) * 2 + 1] };
                    unsigned blf[2] = { bl[j >> 1][(j & 1) * 2], bl[j >> 1][(j & 1) * 2 + 1] };
                    mma_bf16(acc[i][j], ah[i], bhf);
                    mma_bf16(acc[i][j], ah[i], blf);
                    mma_bf16(acc[i][j], al[i], bhf);
                }
        }
        buf = (buf == 2) ? 0 : buf + 1;
        nbuf = (nbuf == 2) ? 0 : nbuf + 1;
    }

#pragma unroll
    for (int i = 0; i < 2; i++) {
        int r0 = m0 + wm * 32 + i * 16 + g;
#pragma unroll
        for (int j = 0; j < 4; j++) {
            int cc = n0 + wn * 32 + j * 8 + 2 * q;
            *(float2*)(g_Xg + (size_t)r0 * N4D + cc)       = make_float2(acc[i][j][0], acc[i][j][1]);
            *(float2*)(g_Xg + (size_t)(r0 + 8) * N4D + cc) = make_float2(acc[i][j][2], acc[i][j][3]);
        }
    }
}

// ---------------- kernel 4: reset state + barriers ----------------
__global__ void reset_kernel() {
    int i = blockIdx.x * 256 + threadIdx.x;
    if (i < 2 * NB * ND / 2) {
        ((unsigned*)g_h16)[i] = 0u;
    }
    if (i < BGRPS * 32) g_arr[i] = 0u;
}

// ---------------- kernel 5: persistent LSTM recurrence ----------------
// 128 CTAs (1/SM) = 4 batch-groups x 32 unit-groups, 256 threads each.
// CTA owns 16 batches x 16 units. W_hh fragments preloaded into REGISTERS
// (64 regs/warp) once; step loop does only A-side ldsm4 + HMMA. Epilogue is
// warp-local via 4 shfl.xor (no gates smem round-trip). Per-batch-group
// 32-CTA grid barrier.
__global__ void __launch_bounds__(256, 1) lstm_rec(const int* __restrict__ lengths) {
    extern __shared__ unsigned smem[];
    char* smc = (char*)smem;
    unsigned* sW = (unsigned*)(smc + SM_W);             // GROWS*WSTRIDE u32

    unsigned sb = (unsigned)__cvta_generic_to_shared(smc);
    unsigned sW_b = sb + SM_W;
    unsigned sH_b = sb + SM_H;

    int t = threadIdx.x, cta = blockIdx.x;
    int wn = t >> 5, lane = t & 31;           // 8 warps, all on N
    int row = lane >> 2, q = lane & 3;

    int bgrp = cta >> 5;            // 0..3
    int ugrp = cta & 31;            // 0..31
    int jbase = ugrp * UNITS;

    // load W_hh slice (fp16) to smem. slot s (0..63): u=s>>2, gate=s&3.
    const unsigned* Wsrc = (const unsigned*)g_Wh16;
    for (int i = t; i < GROWS * 256; i += 256) {
        int s = i >> 8, kw = i & 255;
        int u = s >> 2, gate = s & 3;
        int grow = gate * ND + jbase + u;
        sW[s * WSTRIDE + kw] = Wsrc[grow * 256 + kw];
    }
    __syncthreads();

    // preload all 32 W fragments into registers (loop-invariant B operand)
    unsigned bw[64];
    {
        unsigned boff = sW_b + (unsigned)(wn * 8 + (lane & 7)) * (WSTRIDE * 4)
                      + ((lane >> 3) & 1) * 16;
#pragma unroll
        for (int kc = 0; kc < 32; kc++) ldsm2(&bw[2 * kc], boff + kc * 32);
    }

    // epilogue ownership (warp-local): even-q lanes handle batch `row`,
    // odd-q lanes batch `row+8`; unit = 2*wn + (q>>1).
    int parity = q & 1;
    int b_own = bgrp * BPC + row + (parity ? 8 : 0);
    int jglob = jbase + 2 * wn + (q >> 1);
    int len0 = lengths[b_own] - 1;
    float cst = 0.f;

    // ldmatrix A lane address
    unsigned aoff = sH_b + (unsigned)(lane & 15) * (WSTRIDE * 4) + (lane >> 4) * 16;

    // staging: 16 rows x 1024B, 4 chunks of 256B/row; 1 cp16/thread/chunk
    int sr = t >> 4, ssg = t & 15;
    unsigned sdst0 = sH_b + (unsigned)sr * (WSTRIDE * 4) + ssg * 16;
    size_t ssrc0 = (size_t)sr * 1024 + ssg * 16;

    unsigned* arrp = &g_arr[bgrp * 32];

    // prefetch Xg for step 0
    size_t xb0 = ((size_t)b_own * NS + 0) * N4D + jglob;
    float x0 = __ldcg(g_Xg + xb0);
    float x1 = __ldcg(g_Xg + xb0 + 512);
    float x2 = __ldcg(g_Xg + xb0 + 1024);
    float x3 = __ldcg(g_Xg + xb0 + 1536);

    __syncthreads();

    for (int step = 0; step < NS; step++) {
        int rd = step & 1;
        int wr = rd ^ 1;

        // ---- issue h staging: 4 K-chunks, one commit group each ----
        {
            const char* hsrc = (const char*)g_h16 + (size_t)rd * (NB * ND * 2)
                             + (size_t)bgrp * (BPC * 1024);
#pragma unroll
            for (int c = 0; c < 4; c++) {
                cp16(sdst0 + c * 256, hsrc + ssrc0 + c * 256);
                cp_commit();
            }
        }

        // ---- mma over 4 chunks, overlapped with staging ----
        float acc[4] = {0.f, 0.f, 0.f, 0.f};
#pragma unroll
        for (int c = 0; c < 4; c++) {
            if (c == 0) cp_wait<3>();
            else if (c == 1) cp_wait<2>();
            else if (c == 2) cp_wait<1>();
            else cp_wait<0>();
            __syncthreads();
#pragma unroll
            for (int j = 0; j < 8; j++) {
                int kc = c * 8 + j;
                unsigned ah[4];
                ldsm4(ah, aoff + kc * 32);
                mma_f16(acc, ah, &bw[2 * kc]);
            }
        }

        // ---- warp-local epilogue via shuffles ----
        {
            float s0 = __shfl_xor_sync(0xffffffffu, acc[0], 1);
            float s1 = __shfl_xor_sync(0xffffffffu, acc[1], 1);
            float s2 = __shfl_xor_sync(0xffffffffu, acc[2], 1);
            float s3 = __shfl_xor_sync(0xffffffffu, acc[3], 1);
            float gi, gf, gg_, go;
            if (!parity) { gi = acc[0]; gf = acc[1]; gg_ = s0;     go = s1;     }
            else         { gi = s2;     gf = s3;     gg_ = acc[2]; go = acc[3]; }
            gi += x0; gf += x1; gg_ += x2; go += x3;
            float iv = sigf(gi);
            float fv = sigf(gf);
            float gv = tanhfast(gg_);
            float ov = sigf(go);
            float c = fv * cst + iv * gv;
            cst = c;
            float hv = ov * tanhfast(c);
            g_h16[wr * (NB * ND) + b_own * ND + jglob] = __float2half_rn(hv);
            if (step == len0) g_final[b_own * ND + jglob] = hv;
        }
        __syncthreads();            // all warps' h writes before arrive

        // ---- arrive (group barrier) ----
        if (t == 0) arrive_release(arrp);

        // ---- prefetch next step's Xg while barrier settles ----
        {
            int nstep = (step + 1 < NS) ? step + 1 : 0;
            size_t xb = ((size_t)b_own * NS + nstep) * N4D + jglob;
            x0 = __ldcg(g_Xg + xb);
            x1 = __ldcg(g_Xg + xb + 512);
            x2 = __ldcg(g_Xg + xb + 1024);
            x3 = __ldcg(g_Xg + xb + 1536);
        }

        // ---- wait (32 CTAs of this batch group) ----
        if (t == 0) {
            unsigned target = (unsigned)NGRP * (unsigned)(step + 1);
            while (ld_acquire(arrp) < target) { }
        }
        __syncthreads();
    }
}

// ---------------- kernel 6: output projection ----------------
__global__ void final_out(const float* __restrict__ w_out, const float* __restrict__ b_out,
                          float* __restrict__ out) {
    int b = blockIdx.x;
    int t = threadIdx.x;
    int r = t >> 5, lane = t & 31;
    float s = 0.f;
    for (int k = lane; k < ND; k += 32)
        s += g_final[b * ND + k] * w_out[r * ND + k];
#pragma unroll
    for (int off = 16; off; off >>= 1) s += __shfl_down_sync(0xffffffffu, s, off);
    if (lane == 0) out[b * 2 + r] = s + b_out[r];
}

// ---------------- launch ----------------
extern "C" void kernel_launch(void* const* d_in, const int* in_sizes, int n_in,
                              void* d_out, int out_size) {
    const int*   seqs    = (const int*)d_in[0];
    const int*   lengths = (const int*)d_in[1];
    const float* emb     = (const float*)d_in[2];
    const float* wih     = (const float*)d_in[3];
    const float* whh     = (const float*)d_in[4];
    const float* wout    = (const float*)d_in[5];
    const float* bout    = (const float*)d_in[6];
    float* out = (float*)d_out;

    cudaFuncSetAttribute(lstm_rec, cudaFuncAttributeMaxDynamicSharedMemorySize, SM_TOT);
    const int gemm_smem = GNSTAGE * GSTAGE_B;
    cudaFuncSetAttribute(input_gemm, cudaFuncAttributeMaxDynamicSharedMemorySize, gemm_smem);

    prep_weights<<<4096, 256>>>(wih, whh);
    embed_kernel<<<NVIS, 128>>>(seqs, emb);
    dim3 gg(N4D / 128, NVIS / 128);
    input_gemm<<<gg, 512, gemm_smem>>>();
    reset_kernel<<<128, 256>>>();
    lstm_rec<<<NCTA_REC, 256, SM_TOT>>>(lengths);
    final_out<<<NB, 64>>>(wout, bout, out);
}

// round 10
// speedup vs baseline: 2.8182x; 1.3074x over previous
#include <cuda_runtime.h>
#include <cuda_bf16.h>
#include <cuda_fp16.h>
#include <math.h>

// Problem sizes
#define NB    64
#define NS    256
#define NC    16
#define ND    512
#define N4D   2048
#define NVIS  16384            // NB*NS
#define VOCABI 20000

// Recurrence config: 4 batch-groups x 32 unit-groups = 128 CTAs (1/SM)
#define NCTA_REC 128
#define BGRPS    4
#define BPC      16            // batches per CTA
#define UNITS    16            // hidden units per CTA
#define GROWS    64            // gate rows per CTA (UNITS*4)
#define NGRP     32            // CTAs per batch group
#define WSTRIDE  260           // u32 stride for a 512-half row (+16B pad) = 1040 B
#define ROWB     1040          // bytes per padded smem row

// lstm_rec smem byte offsets
#define SM_WHH  0
#define SM_WSZ  (GROWS * WSTRIDE * 4)               // 66560
#define SM_WIH  SM_WSZ                              // 66560
#define SM_H    (2 * SM_WSZ)                        // 133120
#define SM_HSZ  (BPC * WSTRIDE * 4)                 // 16640
#define SM_X    (SM_H + SM_HSZ)                     // 149760 (2 buffers)
#define SM_TOT  (SM_X + 2 * SM_HSZ)                 // 183040

// ---------------- device scratch (static globals: no allocation) ----------------
__device__ __half        g_Wih16[N4D * ND];
__device__ __half        g_Wh16[N4D * ND];
__device__ __half        g_X16[NVIS * ND];          // [s][b][d] fp16
__device__ __align__(128) __half g_h16[2 * NB * ND]; // double buffered h (fp16)
__device__ float         g_final[NB * ND];
__device__ unsigned      g_arr[BGRPS * 32];          // 4 counters, 128B apart

// ---------------- helpers ----------------
__device__ __forceinline__ void mma_f16(float* c, const unsigned* a, const unsigned* b) {
    asm volatile(
        "mma.sync.aligned.m16n8k16.row.col.f32.f16.f16.f32 "
        "{%0,%1,%2,%3}, {%4,%5,%6,%7}, {%8,%9}, {%0,%1,%2,%3};\n"
        : "+f"(c[0]), "+f"(c[1]), "+f"(c[2]), "+f"(c[3])
        : "r"(a[0]), "r"(a[1]), "r"(a[2]), "r"(a[3]), "r"(b[0]), "r"(b[1]));
}

__device__ __forceinline__ void ldsm4(unsigned* r, unsigned saddr) {
    asm volatile("ldmatrix.sync.aligned.m8n8.x4.shared.b16 {%0,%1,%2,%3}, [%4];"
                 : "=r"(r[0]), "=r"(r[1]), "=r"(r[2]), "=r"(r[3]) : "r"(saddr));
}
__device__ __forceinline__ void ldsm2(unsigned* r, unsigned saddr) {
    asm volatile("ldmatrix.sync.aligned.m8n8.x2.shared.b16 {%0,%1}, [%2];"
                 : "=r"(r[0]), "=r"(r[1]) : "r"(saddr));
}
__device__ __forceinline__ void cp16(unsigned s, const void* g) {
    asm volatile("cp.async.cg.shared.global [%0], [%1], 16;\n" :: "r"(s), "l"(g));
}
__device__ __forceinline__ void cp_commit() {
    asm volatile("cp.async.commit_group;\n" ::: "memory");
}
template<int N> __device__ __forceinline__ void cp_wait() {
    asm volatile("cp.async.wait_group %0;\n" :: "n"(N) : "memory");
}

__device__ __forceinline__ void arrive_release(unsigned* p) {
    asm volatile("red.release.gpu.global.add.u32 [%0], 1;" :: "l"(p) : "memory");
}
__device__ __forceinline__ unsigned ld_acquire(const unsigned* p) {
    unsigned v;
    asm volatile("ld.acquire.gpu.global.u32 %0, [%1];" : "=r"(v) : "l"(p) : "memory");
    return v;
}

__device__ __forceinline__ float sigf(float x) {
    float e = __expf(-x);
    return __fdividef(1.f, 1.f + e);
}
__device__ __forceinline__ float tanhfast(float x) {
    float e = __expf(-2.f * fabsf(x));
    float r = __fdividef(1.f - e, 1.f + e);
    return copysignf(r, x);
}

// ---------------- kernel 1: weight prep (fp32 -> fp16) ----------------
__global__ void prep_weights(const float* __restrict__ wih, const float* __restrict__ whh) {
    int i = blockIdx.x * 256 + threadIdx.x;
    if (i < N4D * ND) {
        g_Wih16[i] = __float2half_rn(wih[i]);
        g_Wh16[i]  = __float2half_rn(whh[i]);
    }
}

// ---------------- kernel 2: embedding-bag sum -> X fp16 [s][b][d] ----------------
__global__ void embed_kernel(const int* __restrict__ seqs, const float* __restrict__ emb) {
    int vis = blockIdx.x;          // vis = b*256 + s
    int t   = threadIdx.x;         // 0..127
    int b = vis >> 8, s = vis & 255;
    const int* sq = seqs + vis * NC;
    float a0 = 0.f, a1 = 0.f, a2 = 0.f, a3 = 0.f;
#pragma unroll
    for (int c = 0; c < NC; c++) {
        int idx = sq[c];
        if (idx >= VOCABI) continue;          // padding row -> zero
        const float* row = emb + (size_t)idx * ND;
        a0 += row[t];
        a1 += row[t + 128];
        a2 += row[t + 256];
        a3 += row[t + 384];
    }
    __half* dst = g_X16 + ((size_t)s * NB + b) * ND;
    dst[t]       = __float2half_rn(a0);
    dst[t + 128] = __float2half_rn(a1);
    dst[t + 256] = __float2half_rn(a2);
    dst[t + 384] = __float2half_rn(a3);
}

// ---------------- kernel 3: reset state + barriers ----------------
__global__ void reset_kernel() {
    int i = blockIdx.x * 256 + threadIdx.x;
    if (i < 2 * NB * ND / 2) {
        ((unsigned*)g_h16)[i] = 0u;
    }
    if (i < BGRPS * 32) g_arr[i] = 0u;
}

// ---------------- kernel 4: persistent fused LSTM ----------------
// 128 CTAs (1/SM) = 4 batch-groups x 32 unit-groups, 256 threads each.
// CTA owns 16 batches x 16 units. gates = x[s]@Wih^T + h[s-1]@Whh^T computed
// per step: both W fragment sets preloaded into registers (128 regs/warp);
// x[s+1] tile (16 KB, fp16) prefetched one step ahead into double-buffered
// smem; h staged per step in 4 K-chunks overlapped with mma. Epilogue is
// warp-local via shfl. Per-batch-group 32-CTA grid barrier.
__global__ void __launch_bounds__(256, 1) lstm_rec(const int* __restrict__ lengths) {
    extern __shared__ unsigned smem[];
    char* smc = (char*)smem;

    unsigned sb = (unsigned)__cvta_generic_to_shared(smc);
    unsigned sH_b = sb + SM_H;
    unsigned sX_b = sb + SM_X;

    int t = threadIdx.x, cta = blockIdx.x;
    int wn = t >> 5, lane = t & 31;           // 8 warps, all on N
    int row = lane >> 2, q = lane & 3;

    int bgrp = cta >> 5;            // 0..3
    int ugrp = cta & 31;            // 0..31
    int jbase = ugrp * UNITS;

    // load W slices (fp16) to smem. slot s (0..63): u=s>>2, gate=s&3.
    {
        unsigned* sWhh = (unsigned*)(smc + SM_WHH);
        unsigned* sWih = (unsigned*)(smc + SM_WIH);
        const unsigned* Hsrc = (const unsigned*)g_Wh16;
        const unsigned* Isrc = (const unsigned*)g_Wih16;
        for (int i = t; i < GROWS * 256; i += 256) {
            int s = i >> 8, kw = i & 255;
            int u = s >> 2, gate = s & 3;
            int grow = gate * ND + jbase + u;
            sWhh[s * WSTRIDE + kw] = Hsrc[grow * 256 + kw];
            sWih[s * WSTRIDE + kw] = Isrc[grow * 256 + kw];
        }
    }
    __syncthreads();

    // preload B fragments for both weight sets (loop-invariant)
    unsigned bwh[64], bwi[64];
    {
        unsigned bl = (unsigned)(wn * 8 + (lane & 7)) * ROWB + ((lane >> 3) & 1) * 16;
        unsigned bh_ = sb + SM_WHH + bl;
        unsigned bi_ = sb + SM_WIH + bl;
#pragma unroll
        for (int kc = 0; kc < 32; kc++) {
            ldsm2(&bwh[2 * kc], bh_ + kc * 32);
            ldsm2(&bwi[2 * kc], bi_ + kc * 32);
        }
    }

    // epilogue ownership (warp-local): even-q lanes batch `row`, odd-q `row+8`;
    // unit = 2*wn + (q>>1).
    int parity = q & 1;
    int b_own = bgrp * BPC + row + (parity ? 8 : 0);
    int jglob = jbase + 2 * wn + (q >> 1);
    int len0 = lengths[b_own] - 1;
    float cst = 0.f;

    // ldmatrix A lane addresses (same pattern for h and x tiles)
    unsigned alane = (unsigned)(lane & 15) * ROWB + (lane >> 4) * 16;
    unsigned ahoff = sH_b + alane;

    // h staging: 16 rows x 1024B, 4 chunks of 256B/row; 1 cp16/thread/chunk
    int sr = t >> 4, ssg = t & 15;
    unsigned sdst0 = sH_b + (unsigned)sr * ROWB + ssg * 16;
    size_t ssrc0 = (size_t)sr * 1024 + ssg * 16;

    unsigned* arrp = &g_arr[bgrp * 32];

    // x tile gmem base for this batch group: 16 rows x 1024B contiguous
    const char* xg_base = (const char*)g_X16 + (size_t)bgrp * (BPC * 1024);

    // prologue: stage x[0] into buffer 0
    {
#pragma unroll
        for (int k = 0; k < 4; k++) {
            int u = t + k * 256;
            int rw = u >> 6, c16 = u & 63;
            cp16(sX_b + (unsigned)rw * ROWB + c16 * 16,
                 xg_base + (size_t)rw * 1024 + c16 * 16);
        }
        cp_commit();
        cp_wait<0>();
    }
    __syncthreads();

    for (int step = 0; step < NS; step++) {
        int rd = step & 1;
        int wr = rd ^ 1;
        unsigned xb = (unsigned)(step & 1);
        unsigned xn = xb ^ 1u;

        // ---- issue h staging: 4 K-chunks, one commit group each ----
        {
            const char* hsrc = (const char*)g_h16 + (size_t)rd * (NB * ND * 2)
                             + (size_t)bgrp * (BPC * 1024);
#pragma unroll
            for (int c = 0; c < 4; c++) {
                cp16(sdst0 + c * 256, hsrc + ssrc0 + c * 256);
                cp_commit();
            }
        }
        // ---- issue x[step+1] prefetch into buffer xn (group 5) ----
        {
            int ns = (step + 1 < NS) ? step + 1 : 0;
            const char* xsrc = xg_base + (size_t)ns * (NB * 1024);
#pragma unroll
            for (int k = 0; k < 4; k++) {
                int u = t + k * 256;
                int rw = u >> 6, c16 = u & 63;
                cp16(sX_b + xn * (unsigned)SM_HSZ + (unsigned)rw * ROWB + c16 * 16,
                     xsrc + (size_t)rw * 1024 + c16 * 16);
            }
            cp_commit();
        }

        float acc[4] = {0.f, 0.f, 0.f, 0.f};

        // ---- x-mma first (x[step] ready in buf xb) — overlaps h arrival ----
        {
            unsigned axoff = sX_b + xb * (unsigned)SM_HSZ + alane;
#pragma unroll
            for (int kc = 0; kc < 32; kc++) {
                unsigned ax[4];
                ldsm4(ax, axoff + kc * 32);
                mma_f16(acc, ax, &bwi[2 * kc]);
            }
        }

        // ---- h-mma over 4 chunks ----
#pragma unroll
        for (int c = 0; c < 4; c++) {
            if (c == 0) cp_wait<4>();
            else if (c == 1) cp_wait<3>();
            else if (c == 2) cp_wait<2>();
            else cp_wait<1>();
            __syncthreads();
#pragma unroll
            for (int j = 0; j < 8; j++) {
                int kc = c * 8 + j;
                unsigned ah[4];
                ldsm4(ah, ahoff + kc * 32);
                mma_f16(acc, ah, &bwh[2 * kc]);
            }
        }

        // ---- warp-local epilogue via shuffles ----
        {
            float s0 = __shfl_xor_sync(0xffffffffu, acc[0], 1);
            float s1 = __shfl_xor_sync(0xffffffffu, acc[1], 1);
            float s2 = __shfl_xor_sync(0xffffffffu, acc[2], 1);
            float s3 = __shfl_xor_sync(0xffffffffu, acc[3], 1);
            float gi, gf, gg_, go;
            if (!parity) { gi = acc[0]; gf = acc[1]; gg_ = s0;     go = s1;     }
            else         { gi = s2;     gf = s3;     gg_ = acc[2]; go = acc[3]; }
            float iv = sigf(gi);
            float fv = sigf(gf);
            float gv = tanhfast(gg_);
            float ov = sigf(go);
            float c = fv * cst + iv * gv;
            cst = c;
            float hv = ov * tanhfast(c);
            g_h16[wr * (NB * ND) + b_own * ND + jglob] = __float2half_rn(hv);
            if (step == len0) g_final[b_own * ND + jglob] = hv;
        }
        cp_wait<0>();               // drain x prefetch (own copies)
        __syncthreads();            // h writes + x tile visible CTA-wide

        // ---- arrive (group barrier) ----
        if (t == 0) arrive_release(arrp);

        // ---- wait (32 CTAs of this batch group) ----
        if (t == 0) {
            unsigned target = (unsigned)NGRP * (unsigned)(step + 1);
            while (ld_acquire(arrp) < target) { }
        }
        __syncthreads();
    }
}

// ---------------- kernel 5: output projection ----------------
__global__ void final_out(const float* __restrict__ w_out, const float* __restrict__ b_out,
                          float* __restrict__ out) {
    int b = blockIdx.x;
    int t = threadIdx.x;
    int r = t >> 5, lane = t & 31;
    float s = 0.f;
    for (int k = lane; k < ND; k += 32)
        s += g_final[b * ND + k] * w_out[r * ND + k];
#pragma unroll
    for (int off = 16; off; off >>= 1) s += __shfl_down_sync(0xffffffffu, s, off);
    if (lane == 0) out[b * 2 + r] = s + b_out[r];
}

// ---------------- launch ----------------
extern "C" void kernel_launch(void* const* d_in, const int* in_sizes, int n_in,
                              void* d_out, int out_size) {
    const int*   seqs    = (const int*)d_in[0];
    const int*   lengths = (const int*)d_in[1];
    const float* emb     = (const float*)d_in[2];
    const float* wih     = (const float*)d_in[3];
    const float* whh     = (const float*)d_in[4];
    const float* wout    = (const float*)d_in[5];
    const float* bout    = (const float*)d_in[6];
    float* out = (float*)d_out;

    cudaFuncSetAttribute(lstm_rec, cudaFuncAttributeMaxDynamicSharedMemorySize, SM_TOT);

    prep_weights<<<4096, 256>>>(wih, whh);
    embed_kernel<<<NVIS, 128>>>(seqs, emb);
    reset_kernel<<<128, 256>>>();
    lstm_rec<<<NCTA_REC, 256, SM_TOT>>>(lengths);
    final_out<<<NB, 64>>>(wout, bout, out);
}

// round 11
// speedup vs baseline: 3.0323x; 1.0760x over previous
#include <cuda_runtime.h>
#include <cuda_fp16.h>
#include <math.h>

// Problem sizes
#define NB    64
#define NS    256
#define NC    16
#define ND    512
#define N4D   2048
#define NVIS  16384            // NB*NS
#define VOCABI 20000

// Recurrence config: 4 batch-groups x 32 unit-groups = 128 CTAs (1/SM)
#define NCTA_REC 128
#define BGRPS    4
#define BPC      16            // batches per CTA
#define UNITS    16            // hidden units per CTA
#define GROWS    64            // gate rows per CTA (UNITS*4)
#define NGRP     32            // CTAs per batch group
#define WSTRIDE  260           // u32 stride for a 512-half row (+16B pad) = 1040 B
#define ROWB     1040          // bytes per padded smem row

// lstm_rec smem byte offsets
#define SM_WHH  0
#define SM_WSZ  (GROWS * WSTRIDE * 4)               // 66560
#define SM_WIH  SM_WSZ                              // 66560
#define SM_H    (2 * SM_WSZ)                        // 133120
#define SM_HSZ  (BPC * WSTRIDE * 4)                 // 16640
#define SM_X    (SM_H + SM_HSZ)                     // 149760 (2 buffers)
#define SM_TOT  (SM_X + 2 * SM_HSZ)                 // 183040

// ---------------- device scratch (static globals: no allocation) ----------------
__device__ __half        g_Wih16[N4D * ND];
__device__ __half        g_Wh16[N4D * ND];
__device__ __half        g_X16[NVIS * ND];          // [s][b][d] fp16
__device__ __align__(128) __half g_h16[2 * NB * ND]; // double buffered h (fp16)
__device__ float         g_final[NB * ND];
__device__ unsigned      g_arr[BGRPS * 32];          // 4 counters, 128B apart

// ---------------- helpers ----------------
__device__ __forceinline__ void mma_f16(float* c, const unsigned* a, const unsigned* b) {
    asm volatile(
        "mma.sync.aligned.m16n8k16.row.col.f32.f16.f16.f32 "
        "{%0,%1,%2,%3}, {%4,%5,%6,%7}, {%8,%9}, {%0,%1,%2,%3};\n"
        : "+f"(c[0]), "+f"(c[1]), "+f"(c[2]), "+f"(c[3])
        : "r"(a[0]), "r"(a[1]), "r"(a[2]), "r"(a[3]), "r"(b[0]), "r"(b[1]));
}

__device__ __forceinline__ void ldsm4(unsigned* r, unsigned saddr) {
    asm volatile("ldmatrix.sync.aligned.m8n8.x4.shared.b16 {%0,%1,%2,%3}, [%4];"
                 : "=r"(r[0]), "=r"(r[1]), "=r"(r[2]), "=r"(r[3]) : "r"(saddr));
}
__device__ __forceinline__ void ldsm2(unsigned* r, unsigned saddr) {
    asm volatile("ldmatrix.sync.aligned.m8n8.x2.shared.b16 {%0,%1}, [%2];"
                 : "=r"(r[0]), "=r"(r[1]) : "r"(saddr));
}
__device__ __forceinline__ void cp16(unsigned s, const void* g) {
    asm volatile("cp.async.cg.shared.global [%0], [%1], 16;\n" :: "r"(s), "l"(g));
}
__device__ __forceinline__ void cp_commit() {
    asm volatile("cp.async.commit_group;\n" ::: "memory");
}
template<int N> __device__ __forceinline__ void cp_wait() {
    asm volatile("cp.async.wait_group %0;\n" :: "n"(N) : "memory");
}

__device__ __forceinline__ void arrive_release(unsigned* p) {
    asm volatile("red.release.gpu.global.add.u32 [%0], 1;" :: "l"(p) : "memory");
}
__device__ __forceinline__ unsigned ld_acquire(const unsigned* p) {
    unsigned v;
    asm volatile("ld.acquire.gpu.global.u32 %0, [%1];" : "=r"(v) : "l"(p) : "memory");
    return v;
}

__device__ __forceinline__ float sigf(float x) {
    float e = __expf(-x);
    return __fdividef(1.f, 1.f + e);
}
__device__ __forceinline__ float tanhfast(float x) {
    float e = __expf(-2.f * fabsf(x));
    float r = __fdividef(1.f - e, 1.f + e);
    return copysignf(r, x);
}

// ---------------- kernel 1: weight prep (fp32 -> fp16) ----------------
__global__ void prep_weights(const float* __restrict__ wih, const float* __restrict__ whh) {
    int i = blockIdx.x * 256 + threadIdx.x;
    if (i < N4D * ND) {
        g_Wih16[i] = __float2half_rn(wih[i]);
        g_Wh16[i]  = __float2half_rn(whh[i]);
    }
}

// ---------------- kernel 2: embedding-bag sum -> X fp16 [s][b][d] ----------------
__global__ void embed_kernel(const int* __restrict__ seqs, const float* __restrict__ emb) {
    int vis = blockIdx.x;          // vis = b*256 + s
    int t   = threadIdx.x;         // 0..127
    int b = vis >> 8, s = vis & 255;
    const int* sq = seqs + vis * NC;
    float a0 = 0.f, a1 = 0.f, a2 = 0.f, a3 = 0.f;
#pragma unroll
    for (int c = 0; c < NC; c++) {
        int idx = sq[c];
        if (idx >= VOCABI) continue;          // padding row -> zero
        const float* row = emb + (size_t)idx * ND;
        a0 += row[t];
        a1 += row[t + 128];
        a2 += row[t + 256];
        a3 += row[t + 384];
    }
    __half* dst = g_X16 + ((size_t)s * NB + b) * ND;
    dst[t]       = __float2half_rn(a0);
    dst[t + 128] = __float2half_rn(a1);
    dst[t + 256] = __float2half_rn(a2);
    dst[t + 384] = __float2half_rn(a3);
}

// ---------------- kernel 3: reset state + barriers ----------------
__global__ void reset_kernel() {
    int i = blockIdx.x * 256 + threadIdx.x;
    if (i < 2 * NB * ND / 2) {
        ((unsigned*)g_h16)[i] = 0u;
    }
    if (i < BGRPS * 32) g_arr[i] = 0u;
}

// ---------------- kernel 4: persistent fused LSTM ----------------
// 128 CTAs (1/SM) = 4 batch-groups x 32 unit-groups, 256 threads each.
// CTA owns 16 batches x 16 units. gates = x[s]@Wih^T + h[s-1]@Whh^T.
// Software-pipelined across the grid barrier: the x-GEMM for step s+1 and
// the x[s+2] prefetch execute inside the barrier-wait window of step s, so
// the per-step critical path is only h-stage -> h-mma -> epilogue -> arrive.
__global__ void __launch_bounds__(256, 1) lstm_rec(const int* __restrict__ lengths) {
    extern __shared__ unsigned smem[];
    char* smc = (char*)smem;

    unsigned sb = (unsigned)__cvta_generic_to_shared(smc);
    unsigned sH_b = sb + SM_H;
    unsigned sX_b = sb + SM_X;

    int t = threadIdx.x, cta = blockIdx.x;
    int wn = t >> 5, lane = t & 31;           // 8 warps, all on N
    int row = lane >> 2, q = lane & 3;

    int bgrp = cta >> 5;            // 0..3
    int ugrp = cta & 31;            // 0..31
    int jbase = ugrp * UNITS;

    // load W slices (fp16) to smem. slot s (0..63): u=s>>2, gate=s&3.
    {
        unsigned* sWhh = (unsigned*)(smc + SM_WHH);
        unsigned* sWih = (unsigned*)(smc + SM_WIH);
        const unsigned* Hsrc = (const unsigned*)g_Wh16;
        const unsigned* Isrc = (const unsigned*)g_Wih16;
        for (int i = t; i < GROWS * 256; i += 256) {
            int s = i >> 8, kw = i & 255;
            int u = s >> 2, gate = s & 3;
            int grow = gate * ND + jbase + u;
            sWhh[s * WSTRIDE + kw] = Hsrc[grow * 256 + kw];
            sWih[s * WSTRIDE + kw] = Isrc[grow * 256 + kw];
        }
    }
    __syncthreads();

    // preload B fragments for both weight sets (loop-invariant)
    unsigned bwh[64], bwi[64];
    {
        unsigned bl = (unsigned)(wn * 8 + (lane & 7)) * ROWB + ((lane >> 3) & 1) * 16;
        unsigned bh_ = sb + SM_WHH + bl;
        unsigned bi_ = sb + SM_WIH + bl;
#pragma unroll
        for (int kc = 0; kc < 32; kc++) {
            ldsm2(&bwh[2 * kc], bh_ + kc * 32);
            ldsm2(&bwi[2 * kc], bi_ + kc * 32);
        }
    }

    // epilogue ownership (warp-local): even-q lanes batch `row`, odd-q `row+8`;
    // unit = 2*wn + (q>>1).
    int parity = q & 1;
    int b_own = bgrp * BPC + row + (parity ? 8 : 0);
    int jglob = jbase + 2 * wn + (q >> 1);
    int len0 = lengths[b_own] - 1;
    float cst = 0.f;

    // ldmatrix A lane addresses (same pattern for h and x tiles)
    unsigned alane = (unsigned)(lane & 15) * ROWB + (lane >> 4) * 16;
    unsigned ahoff = sH_b + alane;

    // h staging: 16 rows x 1024B, 4 chunks of 256B/row; 1 cp16/thread/chunk
    int sr = t >> 4, ssg = t & 15;
    unsigned sdst0 = sH_b + (unsigned)sr * ROWB + ssg * 16;
    size_t ssrc0 = (size_t)sr * 1024 + ssg * 16;

    // x staging addressing: 1 cp16 x 4 per thread
    int xr = t >> 6, xc = t & 63;               // covers 4 rows per pass of 256 thr
    unsigned* arrp = &g_arr[bgrp * 32];

    // x tile gmem base for this batch group
    const char* xg_base = (const char*)g_X16 + (size_t)bgrp * (BPC * 1024);

    float xacc[4];

    // ---- prologue: stage x[0], x-mma it, prefetch x[1] ----
    {
#pragma unroll
        for (int k = 0; k < 4; k++) {
            int rw = xr + k * 4;
            cp16(sX_b + (unsigned)rw * ROWB + xc * 16,
                 xg_base + (size_t)rw * 1024 + xc * 16);
        }
        cp_commit();
        cp_wait<0>();
        __syncthreads();
        xacc[0] = xacc[1] = xacc[2] = xacc[3] = 0.f;
        unsigned axoff = sX_b + alane;
#pragma unroll
        for (int kc = 0; kc < 32; kc++) {
            unsigned ax[4];
            ldsm4(ax, axoff + kc * 32);
            mma_f16(xacc, ax, &bwi[2 * kc]);
        }
        // prefetch x[1] into buffer 1
        const char* xsrc = xg_base + (size_t)1 * (NB * 1024);
#pragma unroll
        for (int k = 0; k < 4; k++) {
            int rw = xr + k * 4;
            cp16(sX_b + (unsigned)SM_HSZ + (unsigned)rw * ROWB + xc * 16,
                 xsrc + (size_t)rw * 1024 + xc * 16);
        }
        cp_commit();
    }

    for (int step = 0; step < NS; step++) {
        int rd = step & 1;
        int wr = rd ^ 1;

        // ---- issue h staging: 4 K-chunks, one commit group each ----
        // pending groups entering: [x-prefetch(step+1)] then c0..c3
        {
            const char* hsrc = (const char*)g_h16 + (size_t)rd * (NB * ND * 2)
                             + (size_t)bgrp * (BPC * 1024);
#pragma unroll
            for (int c = 0; c < 4; c++) {
                cp16(sdst0 + c * 256, hsrc + ssrc0 + c * 256);
                cp_commit();
            }
        }

        // ---- h-mma over 4 chunks into xacc ----
#pragma unroll
        for (int c = 0; c < 4; c++) {
            if (c == 0) cp_wait<3>();
            else if (c == 1) cp_wait<2>();
            else if (c == 2) cp_wait<1>();
            else cp_wait<0>();       // also drains x-prefetch(step+1)
            __syncthreads();
#pragma unroll
            for (int j = 0; j < 8; j++) {
                int kc = c * 8 + j;
                unsigned ah[4];
                ldsm4(ah, ahoff + kc * 32);
                mma_f16(xacc, ah, &bwh[2 * kc]);
            }
        }

        // ---- warp-local epilogue via shuffles ----
        {
            float s0 = __shfl_xor_sync(0xffffffffu, xacc[0], 1);
            float s1 = __shfl_xor_sync(0xffffffffu, xacc[1], 1);
            float s2 = __shfl_xor_sync(0xffffffffu, xacc[2], 1);
            float s3 = __shfl_xor_sync(0xffffffffu, xacc[3], 1);
            float gi, gf, gg_, go;
            if (!parity) { gi = xacc[0]; gf = xacc[1]; gg_ = s0;      go = s1;      }
            else         { gi = s2;      gf = s3;      gg_ = xacc[2]; go = xacc[3]; }
            float iv = sigf(gi);
            float fv = sigf(gf);
            float gv = tanhfast(gg_);
            float ov = sigf(go);
            float c = fv * cst + iv * gv;
            cst = c;
            float hv = ov * tanhfast(c);
            g_h16[wr * (NB * ND) + b_own * ND + jglob] = __float2half_rn(hv);
            if (step == len0) g_final[b_own * ND + jglob] = hv;
        }
        __syncthreads();            // all warps' h writes (and x tile) visible

        if (step == NS - 1) break;  // nothing consumes h after the last step

        // ---- arrive (group barrier) ----
        if (t == 0) arrive_release(arrp);

        // ---- barrier window: prefetch x[step+2], x-mma for step+1 ----
        {
            int ns2 = (step + 2 < NS) ? step + 2 : 0;
            const char* xsrc = xg_base + (size_t)ns2 * (NB * 1024);
            unsigned xpb = (unsigned)(step & 1) * (unsigned)SM_HSZ;   // buf for s+2
#pragma unroll
            for (int k = 0; k < 4; k++) {
                int rw = xr + k * 4;
                cp16(sX_b + xpb + (unsigned)rw * ROWB + xc * 16,
                     xsrc + (size_t)rw * 1024 + xc * 16);
            }
            cp_commit();

            // x-mma for step+1 (tile complete: drained at chunk3 + synced)
            xacc[0] = xacc[1] = xacc[2] = xacc[3] = 0.f;
            unsigned axoff = sX_b + (unsigned)((step + 1) & 1) * (unsigned)SM_HSZ + alane;
#pragma unroll
            for (int kc = 0; kc < 32; kc++) {
                unsigned ax[4];
                ldsm4(ax, axoff + kc * 32);
                mma_f16(xacc, ax, &bwi[2 * kc]);
            }
        }

        // ---- wait (32 CTAs of this batch group) ----
        if (t == 0) {
            unsigned target = (unsigned)NGRP * (unsigned)(step + 1);
            while (ld_acquire(arrp) < target) { }
        }
        __syncthreads();
    }
}

// ---------------- kernel 5: output projection ----------------
__global__ void final_out(const float* __restrict__ w_out, const float* __restrict__ b_out,
                          float* __restrict__ out) {
    int b = blockIdx.x;
    int t = threadIdx.x;
    int r = t >> 5, lane = t & 31;
    float s = 0.f;
    for (int k = lane; k < ND; k += 32)
        s += g_final[b * ND + k] * w_out[r * ND + k];
#pragma unroll
    for (int off = 16; off; off >>= 1) s += __shfl_down_sync(0xffffffffu, s, off);
    if (lane == 0) out[b * 2 + r] = s + b_out[r];
}

// ---------------- launch ----------------
extern "C" void kernel_launch(void* const* d_in, const int* in_sizes, int n_in,
                              void* d_out, int out_size) {
    const int*   seqs    = (const int*)d_in[0];
    const int*   lengths = (const int*)d_in[1];
    const float* emb     = (const float*)d_in[2];
    const float* wih     = (const float*)d_in[3];
    const float* whh     = (const float*)d_in[4];
    const float* wout    = (const float*)d_in[5];
    const float* bout    = (const float*)d_in[6];
    float* out = (float*)d_out;

    cudaFuncSetAttribute(lstm_rec, cudaFuncAttributeMaxDynamicSharedMemorySize, SM_TOT);

    prep_weights<<<4096, 256>>>(wih, whh);
    embed_kernel<<<NVIS, 128>>>(seqs, emb);
    reset_kernel<<<128, 256>>>();
    lstm_rec<<<NCTA_REC, 256, SM_TOT>>>(lengths);
    final_out<<<NB, 64>>>(wout, bout, out);
}